// round 6
// baseline (speedup 1.0000x reference)
#include <cuda_runtime.h>
#include <math.h>

#define SQ 2048
#define EM 512
#define NH 8
#define HD 64
#define EPSF 1e-15f

// ---------------- packed f32x2 helpers (sm_103a FFMA2 path) ----------------
__device__ __forceinline__ unsigned long long pack2(float x, float y) {
    unsigned long long r;
    asm("mov.b64 %0, {%1, %2};" : "=l"(r) : "f"(x), "f"(y));
    return r;
}
__device__ __forceinline__ unsigned long long bcast2(float x) {
    unsigned long long r;
    asm("mov.b64 %0, {%1, %1};" : "=l"(r) : "f"(x));
    return r;
}
__device__ __forceinline__ void ffma2(unsigned long long& d, unsigned long long a,
                                      unsigned long long b) {
    asm("fma.rn.f32x2 %0, %1, %2, %0;" : "+l"(d) : "l"(a), "l"(b));
}
__device__ __forceinline__ float2 unpack2(unsigned long long v) {
    float2 r;
    asm("mov.b64 {%0, %1}, %2;" : "=f"(r.x), "=f"(r.y) : "l"(v));
    return r;
}

// ---------------- scratch (static device globals; no allocation) ----------------
__device__ float g_proj[3][SQ * EM];   // projected (then normalized) q/k/v points, [S][E]
__device__ float g_T[2][EM * SQ];      // q,k transposed to [E][S] for attention tile loads
__device__ float g_x2[3][SQ];          // per-token ||x||^2 of the raw inputs
__device__ float g_zn[3][EM];          // column norms of W
__device__ float g_chv[3][EM];         // cosh(2*r)
__device__ float g_shv[3][EM];         // sinh(2*r)
__device__ float g_pt2[3][NH * SQ];    // per-head ||point||^2 after normalization
__device__ float g_rinv[3][NH * SQ];   // 1/(1 - pt2)

// ---------------- kernel 1: W column norms + bias cosh/sinh ----------------
__global__ void colnorm_k(const float* __restrict__ W0, const float* __restrict__ W1,
                          const float* __restrict__ W2, const float* __restrict__ b0,
                          const float* __restrict__ b1, const float* __restrict__ b2) {
    int t = blockIdx.y;
    int j = blockIdx.x * blockDim.x + threadIdx.x;
    if (j >= EM) return;
    const float* W = (t == 0) ? W0 : ((t == 1) ? W1 : W2);
    const float* b = (t == 0) ? b0 : ((t == 1) ? b1 : b2);
    float s = 0.f;
    for (int i = 0; i < EM; i++) { float v = W[i * EM + j]; s = fmaf(v, v, s); }
    float zn = fmaxf(sqrtf(s), EPSF);
    float r2 = 2.f * b[j];
    g_zn[t][j] = zn;
    g_chv[t][j] = coshf(r2);
    g_shv[t][j] = sinhf(r2);
}

// ---------------- kernel 2: per-token input squared norms ----------------
__global__ void rownorm_k(const float* __restrict__ x0, const float* __restrict__ x1,
                          const float* __restrict__ x2) {
    int t = blockIdx.y, s = blockIdx.x, lane = threadIdx.x;
    const float* x = (t == 0) ? x0 : ((t == 1) ? x1 : x2);
    const float4* row = (const float4*)(x + (size_t)s * EM);
    float acc = 0.f;
    for (int i = lane; i < EM / 4; i += 32) {
        float4 v = row[i];
        acc += v.x * v.x + v.y * v.y + v.z * v.z + v.w * v.w;
    }
    #pragma unroll
    for (int m = 16; m; m >>= 1) acc += __shfl_xor_sync(0xffffffffu, acc, m);
    if (lane == 0) g_x2[t][s] = acc;
}

// ---------------- kernel 3: projection GEMM (FFMA2) + h_linear epilogue ----------------
__global__ __launch_bounds__(256) void proj_k(
    const float* __restrict__ x0, const float* __restrict__ x1, const float* __restrict__ x2,
    const float* __restrict__ W0, const float* __restrict__ W1, const float* __restrict__ W2) {
    int t = blockIdx.z;
    const float* X = (t == 0) ? x0 : ((t == 1) ? x1 : x2);
    const float* W = (t == 0) ? W0 : ((t == 1) ? W1 : W2);
    int n0 = blockIdx.x * 64, m0 = blockIdx.y * 64;
    __shared__ float aT[16][68];
    __shared__ float bS[16][68];
    int tid = threadIdx.x;
    int tx = tid & 15, ty = tid >> 4;
    unsigned long long acc2[4][2] = {};
    for (int k0 = 0; k0 < EM; k0 += 16) {
        {
            int m = tid >> 2, kb = (tid & 3) * 4;
            float4 v = *(const float4*)(X + (size_t)(m0 + m) * EM + k0 + kb);
            aT[kb + 0][m] = v.x; aT[kb + 1][m] = v.y; aT[kb + 2][m] = v.z; aT[kb + 3][m] = v.w;
            int kk = tid >> 4, nb = (tid & 15) * 4;
            *(float4*)(&bS[kk][nb]) = *(const float4*)(W + (size_t)(k0 + kk) * EM + n0 + nb);
        }
        __syncthreads();
        #pragma unroll
        for (int kk = 0; kk < 16; kk++) {
            float4 a4 = *(const float4*)(&aT[kk][ty * 4]);
            unsigned long long b01 = *(const unsigned long long*)(&bS[kk][tx * 4]);
            unsigned long long b23 = *(const unsigned long long*)(&bS[kk][tx * 4 + 2]);
            float av[4] = {a4.x, a4.y, a4.z, a4.w};
            #pragma unroll
            for (int j = 0; j < 4; j++) {
                unsigned long long aa = bcast2(av[j]);
                ffma2(acc2[j][0], aa, b01);
                ffma2(acc2[j][1], aa, b23);
            }
        }
        __syncthreads();
    }
    // epilogue: w = sinh(2*zn*asinh(inner*lam/zn*cosh(2r) - (lam-1)*sinh(2r)))
    int col_base = n0 + tx * 4;
    float rzn[4], chr[4], shr[4], znr[4];
    #pragma unroll
    for (int i = 0; i < 4; i++) {
        znr[i] = g_zn[t][col_base + i];
        rzn[i] = 1.f / znr[i];
        chr[i] = g_chv[t][col_base + i];
        shr[i] = g_shv[t][col_base + i];
    }
    #pragma unroll
    for (int j = 0; j < 4; j++) {
        int row = m0 + ty * 4 + j;
        float x2 = g_x2[t][row];
        float lam = 2.f / (1.f - x2);
        float2 p0 = unpack2(acc2[j][0]);
        float2 p1 = unpack2(acc2[j][1]);
        float accv[4] = {p0.x, p0.y, p1.x, p1.y};
        #pragma unroll
        for (int i = 0; i < 4; i++) {
            float arg = (accv[i] * lam * rzn[i]) * chr[i] - (lam - 1.f) * shr[i];
            float dd = 2.f * znr[i] * asinhf(arg);
            g_proj[t][(size_t)row * EM + col_base + i] = sinhf(dd);
        }
    }
}

// ---------------- kernel 4: ball normalization + per-head aux ----------------
__global__ void normaux_k() {
    int t = blockIdx.y, s = blockIdx.x, tid = threadIdx.x;  // 128 threads
    float* row = &g_proj[t][(size_t)s * EM];
    float4 v = ((float4*)row)[tid];
    float l4 = v.x * v.x + v.y * v.y + v.z * v.z + v.w * v.w;
    float tot = l4;
    #pragma unroll
    for (int m = 16; m; m >>= 1) tot += __shfl_xor_sync(0xffffffffu, tot, m);
    __shared__ float wsum[4];
    if ((tid & 31) == 0) wsum[tid >> 5] = tot;
    __syncthreads();
    float total = wsum[0] + wsum[1] + wsum[2] + wsum[3];
    float scale = 1.f / (1.f + sqrtf(1.f + total));
    v.x *= scale; v.y *= scale; v.z *= scale; v.w *= scale;
    ((float4*)row)[tid] = v;
    // per-head sumsq: head = tid/16 (16 threads x 4 cols = 64 cols)
    float hs = l4;
    #pragma unroll
    for (int m = 8; m; m >>= 1) hs += __shfl_xor_sync(0xffffffffu, hs, m);
    if ((tid & 15) == 0) {
        int h = tid >> 4;
        float pt2 = scale * scale * hs;
        g_pt2[t][h * SQ + s] = pt2;
        g_rinv[t][h * SQ + s] = 1.f / (1.f - pt2);
    }
}

// ---------------- kernel 5: transpose q,k to [E][S] ----------------
__global__ void transpose_k() {
    int t = blockIdx.z;  // 0:q 1:k
    __shared__ float tile[32][33];
    int c0 = blockIdx.x * 32, r0 = blockIdx.y * 32;
    int x = threadIdx.x, y = threadIdx.y;  // (32, 8)
    const float* src = g_proj[t];
    #pragma unroll
    for (int yy = y; yy < 32; yy += 8) tile[yy][x] = src[(size_t)(r0 + yy) * EM + c0 + x];
    __syncthreads();
    float* dst = g_T[t];
    #pragma unroll
    for (int yy = y; yy < 32; yy += 8) dst[(size_t)(c0 + yy) * SQ + r0 + x] = tile[x][yy];
}

// ---------------- kernel 6: causal hyperbolic attention + gyromidpoint ----------------
#define TPAD 68
#define ATTN_SMEM_FLOATS (4 * 64 * TPAD + 5 * 64)

__global__ __launch_bounds__(256) void attn_k(const float* __restrict__ stau,
                                              const float* __restrict__ sgam,
                                              float beta, float* __restrict__ out) {
    int bid = blockIdx.x;
    int h = bid & (NH - 1);
    int qt = (SQ / 64 - 1) - (bid >> 3);  // big q-tiles first for load balance
    int q0 = qt * 64;
    extern __shared__ float smem[];
    float* qT = smem;                 // [64 kk][TPAD]
    float* kT = qT + 64 * TPAD;       // [64 kk][TPAD]
    float* vS = kT + 64 * TPAD;       // [64 k ][TPAD]
    float* wS = vS + 64 * TPAD;       // [64 q ][TPAD]  (holds w*lamv)
    float* q2s = wS + 64 * TPAD;
    float* rqs = q2s + 64;
    float* k2s = rqs + 64;
    float* rks = k2s + 64;
    float* lvs = rks + 64;
    int tid = threadIdx.x, tx = tid & 15, ty = tid >> 4;
    float tau = __expf(stau[0]);
    float gamma = sgam[0];

    // load q tile (transposed layout: contiguous in token index)
    {
        int kk = tid >> 3, r8 = (tid & 7) * 8;
        const float* src = &g_T[0][(size_t)(h * HD) * SQ + q0];
        #pragma unroll
        for (int p = 0; p < 2; p++) {
            int K = kk + 32 * p;
            *(float4*)(&qT[K * TPAD + r8])     = *(const float4*)(src + (size_t)K * SQ + r8);
            *(float4*)(&qT[K * TPAD + r8 + 4]) = *(const float4*)(src + (size_t)K * SQ + r8 + 4);
        }
        if (tid < 64) {
            q2s[tid] = g_pt2[0][h * SQ + q0 + tid];
            rqs[tid] = g_rinv[0][h * SQ + q0 + tid];
        }
    }
    __syncthreads();
    float q2r[4], rqr[4];
    #pragma unroll
    for (int j = 0; j < 4; j++) { q2r[j] = q2s[ty * 4 + j]; rqr[j] = rqs[ty * 4 + j]; }

    unsigned long long num2[4][2] = {};
    float den[4] = {};

    for (int kt = 0; kt <= qt; kt++) {
        int k0 = kt * 64;
        {   // load k (transposed) + v (natural) tiles + per-key aux
            int kk = tid >> 3, r8 = (tid & 7) * 8;
            const float* ksrc = &g_T[1][(size_t)(h * HD) * SQ + k0];
            #pragma unroll
            for (int p = 0; p < 2; p++) {
                int K = kk + 32 * p;
                *(float4*)(&kT[K * TPAD + r8])     = *(const float4*)(ksrc + (size_t)K * SQ + r8);
                *(float4*)(&kT[K * TPAD + r8 + 4]) = *(const float4*)(ksrc + (size_t)K * SQ + r8 + 4);
            }
            const float* vsrc = &g_proj[2][(size_t)k0 * EM + h * HD];
            #pragma unroll
            for (int p = 0; p < 2; p++) {
                int R = (tid >> 3) + 32 * p;
                int c8 = (tid & 7) * 8;
                *(float4*)(&vS[R * TPAD + c8])     = *(const float4*)(vsrc + (size_t)R * EM + c8);
                *(float4*)(&vS[R * TPAD + c8 + 4]) = *(const float4*)(vsrc + (size_t)R * EM + c8 + 4);
            }
            if (tid < 64) {
                k2s[tid] = g_pt2[1][h * SQ + k0 + tid];
                rks[tid] = g_rinv[1][h * SQ + k0 + tid];
                lvs[tid] = 2.f * g_rinv[2][h * SQ + k0 + tid];
            }
        }
        __syncthreads();

        // phase 1: qk = Q.K^T over hd=64 (FFMA2)
        unsigned long long qk2[4][2] = {};
        #pragma unroll 8
        for (int kk = 0; kk < 64; kk++) {
            float4 a4 = *(const float4*)(&qT[kk * TPAD + ty * 4]);
            unsigned long long b01 = *(const unsigned long long*)(&kT[kk * TPAD + tx * 4]);
            unsigned long long b23 = *(const unsigned long long*)(&kT[kk * TPAD + tx * 4 + 2]);
            float av[4] = {a4.x, a4.y, a4.z, a4.w};
            #pragma unroll
            for (int j = 0; j < 4; j++) {
                unsigned long long aa = bcast2(av[j]);
                ffma2(qk2[j][0], aa, b01);
                ffma2(qk2[j][1], aa, b23);
            }
        }

        // per-key aux into regs
        float k2r[4], rkr[4], lvr[4];
        #pragma unroll
        for (int i = 0; i < 4; i++) {
            k2r[i] = k2s[tx * 4 + i]; rkr[i] = rks[tx * 4 + i]; lvr[i] = lvs[tx * 4 + i];
        }
        bool diag = (kt == qt);

        // transform: Poincare distance -> exp weight; stage w*lamv to smem
        #pragma unroll
        for (int j = 0; j < 4; j++) {
            int qg = q0 + ty * 4 + j;
            float2 p0 = unpack2(qk2[j][0]);
            float2 p1 = unpack2(qk2[j][1]);
            float qkv[4] = {p0.x, p0.y, p1.x, p1.y};
            #pragma unroll
            for (int i = 0; i < 4; i++) {
                int kg = k0 + tx * 4 + i;
                float w;
                if (diag && kg > qg) {
                    w = 0.f;
                } else {
                    float d2 = fmaxf(q2r[j] + k2r[i] - 2.f * qkv[i], 0.f);
                    float arg = fmaf(2.f * d2, rqr[j] * rkr[i], 1.f);
                    arg = fmaxf(arg, 1.f + 1e-7f);
                    float dist = __logf(arg + sqrtf((arg - 1.f) * (arg + 1.f)));
                    w = __expf(-tau * dist - gamma);
                }
                float wl = w * lvr[i];
                wS[(ty * 4 + j) * TPAD + tx * 4 + i] = wl;
                den[j] += wl - w;  // = w*(lamv-1)
            }
        }
        __syncthreads();

        // phase 2: num += W_l . V (FFMA2)
        #pragma unroll 4
        for (int kk = 0; kk < 64; kk += 4) {
            float4 w0 = *(const float4*)(&wS[(ty * 4 + 0) * TPAD + kk]);
            float4 w1 = *(const float4*)(&wS[(ty * 4 + 1) * TPAD + kk]);
            float4 w2 = *(const float4*)(&wS[(ty * 4 + 2) * TPAD + kk]);
            float4 w3 = *(const float4*)(&wS[(ty * 4 + 3) * TPAD + kk]);
            float wa[4][4] = {{w0.x, w0.y, w0.z, w0.w}, {w1.x, w1.y, w1.z, w1.w},
                              {w2.x, w2.y, w2.z, w2.w}, {w3.x, w3.y, w3.z, w3.w}};
            #pragma unroll
            for (int c = 0; c < 4; c++) {
                unsigned long long v01 =
                    *(const unsigned long long*)(&vS[(kk + c) * TPAD + tx * 4]);
                unsigned long long v23 =
                    *(const unsigned long long*)(&vS[(kk + c) * TPAD + tx * 4 + 2]);
                #pragma unroll
                for (int j = 0; j < 4; j++) {
                    unsigned long long ww = bcast2(wa[j][c]);
                    ffma2(num2[j][0], ww, v01);
                    ffma2(num2[j][1], ww, v23);
                }
            }
        }
        __syncthreads();
    }

    // epilogue: reduce den & ||g|| across the 16 tx lanes, Mobius half + beta-concat
    #pragma unroll
    for (int j = 0; j < 4; j++) {
        float d = den[j];
        #pragma unroll
        for (int m = 8; m; m >>= 1) d += __shfl_xor_sync(0xffffffffu, d, m);
        d = fmaxf(d, EPSF);
        float inv = 1.f / d;
        float2 p0 = unpack2(num2[j][0]);
        float2 p1 = unpack2(num2[j][1]);
        float numv[4] = {p0.x, p0.y, p1.x, p1.y};
        float g[4];
        float gs = 0.f;
        #pragma unroll
        for (int i = 0; i < 4; i++) { g[i] = numv[i] * inv; gs += g[i] * g[i]; }
        #pragma unroll
        for (int m = 8; m; m >>= 1) gs += __shfl_xor_sync(0xffffffffu, gs, m);
        float gn = fmaxf(sqrtf(gs), EPSF);
        float xc = fminf(gn, 1.f - 1e-7f);
        float tt = xc / (1.f + sqrtf(1.f - xc * xc));  // tanh(0.5*atanh(xc))
        float f = beta * tt / gn;
        int qg = q0 + ty * 4 + j;
        #pragma unroll
        for (int i = 0; i < 4; i++)
            out[(size_t)qg * EM + h * HD + tx * 4 + i] = f * g[i];
    }
}

// ---------------- launch ----------------
extern "C" void kernel_launch(void* const* d_in, const int* in_sizes, int n_in,
                              void* d_out, int out_size) {
    const float* q  = (const float*)d_in[0];
    const float* k  = (const float*)d_in[1];
    const float* v  = (const float*)d_in[2];
    const float* Wq = (const float*)d_in[3];
    const float* Wk = (const float*)d_in[4];
    const float* Wv = (const float*)d_in[5];
    const float* bq = (const float*)d_in[6];
    const float* bk = (const float*)d_in[7];
    const float* bv = (const float*)d_in[8];
    const float* st = (const float*)d_in[9];
    const float* sg = (const float*)d_in[10];
    float* out = (float*)d_out;

    // beta(E/2,1/2) / beta(hd/2,1/2) via lgamma (host)
    double lb = (lgamma(256.0) + lgamma(0.5) - lgamma(256.5))
              - (lgamma(32.0) + lgamma(0.5) - lgamma(32.5));
    float beta = (float)exp(lb);

    cudaFuncSetAttribute(attn_k, cudaFuncAttributeMaxDynamicSharedMemorySize,
                         ATTN_SMEM_FLOATS * (int)sizeof(float));

    colnorm_k<<<dim3(2, 3), 256>>>(Wq, Wk, Wv, bq, bk, bv);
    rownorm_k<<<dim3(SQ, 3), 32>>>(q, k, v);
    proj_k<<<dim3(EM / 64, SQ / 64, 3), 256>>>(q, k, v, Wq, Wk, Wv);
    normaux_k<<<dim3(SQ, 3), 128>>>();
    transpose_k<<<dim3(EM / 32, SQ / 32, 2), dim3(32, 8)>>>();
    attn_k<<<(SQ / 64) * NH, 256, ATTN_SMEM_FLOATS * (int)sizeof(float)>>>(st, sg, beta, out);
    (void)in_sizes; (void)n_in; (void)out_size;
}

// round 7
// speedup vs baseline: 1.5715x; 1.5715x over previous
#include <cuda_runtime.h>
#include <math.h>

#define SQ 2048
#define EM 512
#define NH 8
#define HD 64
#define EPSF 1e-15f

// ---------------- scratch (static device globals; no allocation) ----------------
__device__ float g_proj[3][SQ * EM];   // projected (then normalized) q/k/v points, [S][E]
__device__ float g_T[2][EM * SQ];      // q,k transposed to [E][S] for attention tile loads
__device__ float g_x2[3][SQ];          // per-token ||x||^2 of the raw inputs
__device__ float g_zn[3][EM];          // column norms of W
__device__ float g_chv[3][EM];         // cosh(2*r)
__device__ float g_shv[3][EM];         // sinh(2*r)
__device__ float g_pt2[3][NH * SQ];    // per-head ||point||^2 after normalization
__device__ float g_rinv[3][NH * SQ];   // 1/(1 - pt2)

// ---------------- kernel 1: W column norms + bias cosh/sinh ----------------
__global__ void colnorm_k(const float* __restrict__ W0, const float* __restrict__ W1,
                          const float* __restrict__ W2, const float* __restrict__ b0,
                          const float* __restrict__ b1, const float* __restrict__ b2) {
    int t = blockIdx.y;
    int j = blockIdx.x * blockDim.x + threadIdx.x;
    if (j >= EM) return;
    const float* W = (t == 0) ? W0 : ((t == 1) ? W1 : W2);
    const float* b = (t == 0) ? b0 : ((t == 1) ? b1 : b2);
    float s = 0.f;
    for (int i = 0; i < EM; i++) { float v = W[i * EM + j]; s = fmaf(v, v, s); }
    float zn = fmaxf(sqrtf(s), EPSF);
    float r2 = 2.f * b[j];
    g_zn[t][j] = zn;
    g_chv[t][j] = coshf(r2);
    g_shv[t][j] = sinhf(r2);
}

// ---------------- kernel 2: per-token input squared norms ----------------
__global__ void rownorm_k(const float* __restrict__ x0, const float* __restrict__ x1,
                          const float* __restrict__ x2) {
    int t = blockIdx.y, s = blockIdx.x, lane = threadIdx.x;
    const float* x = (t == 0) ? x0 : ((t == 1) ? x1 : x2);
    const float4* row = (const float4*)(x + (size_t)s * EM);
    float acc = 0.f;
    for (int i = lane; i < EM / 4; i += 32) {
        float4 v = row[i];
        acc += v.x * v.x + v.y * v.y + v.z * v.z + v.w * v.w;
    }
    #pragma unroll
    for (int m = 16; m; m >>= 1) acc += __shfl_xor_sync(0xffffffffu, acc, m);
    if (lane == 0) g_x2[t][s] = acc;
}

// ---------------- kernel 3: projection GEMM + fast h_linear epilogue ----------------
__global__ __launch_bounds__(256) void proj_k(
    const float* __restrict__ x0, const float* __restrict__ x1, const float* __restrict__ x2,
    const float* __restrict__ W0, const float* __restrict__ W1, const float* __restrict__ W2) {
    int t = blockIdx.z;
    const float* X = (t == 0) ? x0 : ((t == 1) ? x1 : x2);
    const float* W = (t == 0) ? W0 : ((t == 1) ? W1 : W2);
    int n0 = blockIdx.x * 64, m0 = blockIdx.y * 64;
    __shared__ float aT[16][68];
    __shared__ float bS[16][68];
    int tid = threadIdx.x;
    int tx = tid & 15, ty = tid >> 4;
    float acc[4][4] = {};
    for (int k0 = 0; k0 < EM; k0 += 16) {
        {
            int m = tid >> 2, kb = (tid & 3) * 4;
            float4 v = *(const float4*)(X + (size_t)(m0 + m) * EM + k0 + kb);
            aT[kb + 0][m] = v.x; aT[kb + 1][m] = v.y; aT[kb + 2][m] = v.z; aT[kb + 3][m] = v.w;
            int kk = tid >> 4, nb = (tid & 15) * 4;
            *(float4*)(&bS[kk][nb]) = *(const float4*)(W + (size_t)(k0 + kk) * EM + n0 + nb);
        }
        __syncthreads();
        #pragma unroll
        for (int kk = 0; kk < 16; kk++) {
            float4 a4 = *(const float4*)(&aT[kk][ty * 4]);
            float4 b4 = *(const float4*)(&bS[kk][tx * 4]);
            float av[4] = {a4.x, a4.y, a4.z, a4.w};
            float bv[4] = {b4.x, b4.y, b4.z, b4.w};
            #pragma unroll
            for (int j = 0; j < 4; j++)
                #pragma unroll
                for (int i = 0; i < 4; i++) acc[j][i] = fmaf(av[j], bv[i], acc[j][i]);
        }
        __syncthreads();
    }
    // epilogue: w = sinh(2*zn*asinh(inner*lam/zn*cosh(2r) - (lam-1)*sinh(2r)))
    // fast forms: asinh(x)=log(x+sqrt(x^2+1)) via __logf; sinh(x)=0.5(e^x-e^-x) via __expf
    int col_base = n0 + tx * 4;
    float znr[4], rzn[4], chr[4], shr[4];
    #pragma unroll
    for (int i = 0; i < 4; i++) {
        znr[i] = g_zn[t][col_base + i];
        rzn[i] = 1.f / znr[i];
        chr[i] = g_chv[t][col_base + i];
        shr[i] = g_shv[t][col_base + i];
    }
    #pragma unroll
    for (int j = 0; j < 4; j++) {
        int row = m0 + ty * 4 + j;
        float x2 = g_x2[t][row];
        float lam = 2.f / (1.f - x2);
        #pragma unroll
        for (int i = 0; i < 4; i++) {
            float arg = (acc[j][i] * lam * rzn[i]) * chr[i] - (lam - 1.f) * shr[i];
            float as = __logf(arg + sqrtf(fmaf(arg, arg, 1.f)));   // asinh
            float dd = 2.f * znr[i] * as;
            float e = __expf(dd);
            g_proj[t][(size_t)row * EM + col_base + i] = 0.5f * (e - 1.f / e);  // sinh
        }
    }
}

// ---------------- kernel 4: ball normalization + per-head aux ----------------
__global__ void normaux_k() {
    int t = blockIdx.y, s = blockIdx.x, tid = threadIdx.x;  // 128 threads
    float* row = &g_proj[t][(size_t)s * EM];
    float4 v = ((float4*)row)[tid];
    float l4 = v.x * v.x + v.y * v.y + v.z * v.z + v.w * v.w;
    float tot = l4;
    #pragma unroll
    for (int m = 16; m; m >>= 1) tot += __shfl_xor_sync(0xffffffffu, tot, m);
    __shared__ float wsum[4];
    if ((tid & 31) == 0) wsum[tid >> 5] = tot;
    __syncthreads();
    float total = wsum[0] + wsum[1] + wsum[2] + wsum[3];
    float scale = 1.f / (1.f + sqrtf(1.f + total));
    v.x *= scale; v.y *= scale; v.z *= scale; v.w *= scale;
    ((float4*)row)[tid] = v;
    // per-head sumsq: head = tid/16 (16 threads x 4 cols = 64 cols)
    float hs = l4;
    #pragma unroll
    for (int m = 8; m; m >>= 1) hs += __shfl_xor_sync(0xffffffffu, hs, m);
    if ((tid & 15) == 0) {
        int h = tid >> 4;
        float pt2 = scale * scale * hs;
        g_pt2[t][h * SQ + s] = pt2;
        g_rinv[t][h * SQ + s] = 1.f / (1.f - pt2);
    }
}

// ---------------- kernel 5: transpose q,k to [E][S] ----------------
__global__ void transpose_k() {
    int t = blockIdx.z;  // 0:q 1:k
    __shared__ float tile[32][33];
    int c0 = blockIdx.x * 32, r0 = blockIdx.y * 32;
    int x = threadIdx.x, y = threadIdx.y;  // (32, 8)
    const float* src = g_proj[t];
    #pragma unroll
    for (int yy = y; yy < 32; yy += 8) tile[yy][x] = src[(size_t)(r0 + yy) * EM + c0 + x];
    __syncthreads();
    float* dst = g_T[t];
    #pragma unroll
    for (int yy = y; yy < 32; yy += 8) dst[(size_t)(c0 + yy) * SQ + r0 + x] = tile[x][yy];
}

// ---------------- kernel 6: causal hyperbolic attention + gyromidpoint ----------------
#define TPAD 68
#define ATTN_SMEM_FLOATS (4 * 64 * TPAD + 5 * 64)

__global__ __launch_bounds__(256) void attn_k(const float* __restrict__ stau,
                                              const float* __restrict__ sgam,
                                              float beta, float* __restrict__ out) {
    // Balanced bid -> (q-tile level w = qt+1 in [1..32], head h) schedule.
    // Placement: bid and bid+148 land on the same SM (same LUT slot). Pairs sum
    // to 28 work units; unpaired bids 108..147 get the big levels 28..32 alone.
    int bid = blockIdx.x;
    int w, h;
    if (bid < 104)      { w = 1 + (bid >> 3);          h = bid & 7; }
    else if (bid < 108) { w = 14;                      h = bid - 104; }       // h 0..3
    else if (bid < 148) { w = 28 + ((bid - 108) >> 3); h = (bid - 108) & 7; } // singles
    else {
        int p = bid - 148;
        if (p < 104) { w = 27 - (p >> 3); h = p & 7; }
        else         { w = 14;            h = p - 104 + 4; }                   // h 4..7
    }
    int qt = w - 1;
    int q0 = qt * 64;
    extern __shared__ float smem[];
    float* qT = smem;                 // [64 kk][TPAD]
    float* kT = qT + 64 * TPAD;       // [64 kk][TPAD]
    float* vS = kT + 64 * TPAD;       // [64 k ][TPAD]
    float* wS = vS + 64 * TPAD;       // [64 q ][TPAD]  (holds w*lamv)
    float* q2s = wS + 64 * TPAD;
    float* rqs = q2s + 64;
    float* k2s = rqs + 64;
    float* rks = k2s + 64;
    float* lvs = rks + 64;
    int tid = threadIdx.x, tx = tid & 15, ty = tid >> 4;
    float tau = __expf(stau[0]);
    float gamma = sgam[0];

    // load q tile (transposed layout: contiguous in token index)
    {
        int kk = tid >> 3, r8 = (tid & 7) * 8;
        const float* src = &g_T[0][(size_t)(h * HD) * SQ + q0];
        #pragma unroll
        for (int p = 0; p < 2; p++) {
            int K = kk + 32 * p;
            *(float4*)(&qT[K * TPAD + r8])     = *(const float4*)(src + (size_t)K * SQ + r8);
            *(float4*)(&qT[K * TPAD + r8 + 4]) = *(const float4*)(src + (size_t)K * SQ + r8 + 4);
        }
        if (tid < 64) {
            q2s[tid] = g_pt2[0][h * SQ + q0 + tid];
            rqs[tid] = g_rinv[0][h * SQ + q0 + tid];
        }
    }
    __syncthreads();
    float q2r[4], rqr[4];
    #pragma unroll
    for (int j = 0; j < 4; j++) { q2r[j] = q2s[ty * 4 + j]; rqr[j] = rqs[ty * 4 + j]; }

    float num[4][4] = {};
    float den[4] = {};

    for (int kt = 0; kt <= qt; kt++) {
        int k0 = kt * 64;
        {   // load k (transposed) + v (natural) tiles + per-key aux
            int kk = tid >> 3, r8 = (tid & 7) * 8;
            const float* ksrc = &g_T[1][(size_t)(h * HD) * SQ + k0];
            #pragma unroll
            for (int p = 0; p < 2; p++) {
                int K = kk + 32 * p;
                *(float4*)(&kT[K * TPAD + r8])     = *(const float4*)(ksrc + (size_t)K * SQ + r8);
                *(float4*)(&kT[K * TPAD + r8 + 4]) = *(const float4*)(ksrc + (size_t)K * SQ + r8 + 4);
            }
            const float* vsrc = &g_proj[2][(size_t)k0 * EM + h * HD];
            #pragma unroll
            for (int p = 0; p < 2; p++) {
                int R = (tid >> 3) + 32 * p;
                int c8 = (tid & 7) * 8;
                *(float4*)(&vS[R * TPAD + c8])     = *(const float4*)(vsrc + (size_t)R * EM + c8);
                *(float4*)(&vS[R * TPAD + c8 + 4]) = *(const float4*)(vsrc + (size_t)R * EM + c8 + 4);
            }
            if (tid < 64) {
                k2s[tid] = g_pt2[1][h * SQ + k0 + tid];
                rks[tid] = g_rinv[1][h * SQ + k0 + tid];
                lvs[tid] = 2.f * g_rinv[2][h * SQ + k0 + tid];
            }
        }
        __syncthreads();

        // phase 1: qk = Q.K^T over hd=64
        float qk[4][4] = {};
        #pragma unroll 8
        for (int kk = 0; kk < 64; kk++) {
            float4 a4 = *(const float4*)(&qT[kk * TPAD + ty * 4]);
            float4 b4 = *(const float4*)(&kT[kk * TPAD + tx * 4]);
            float av[4] = {a4.x, a4.y, a4.z, a4.w};
            float bv[4] = {b4.x, b4.y, b4.z, b4.w};
            #pragma unroll
            for (int j = 0; j < 4; j++)
                #pragma unroll
                for (int i = 0; i < 4; i++) qk[j][i] = fmaf(av[j], bv[i], qk[j][i]);
        }

        // per-key aux into regs
        float k2r[4], rkr[4], lvr[4];
        #pragma unroll
        for (int i = 0; i < 4; i++) {
            k2r[i] = k2s[tx * 4 + i]; rkr[i] = rks[tx * 4 + i]; lvr[i] = lvs[tx * 4 + i];
        }
        bool diag = (kt == qt);

        // transform: Poincare distance -> exp weight; stage w*lamv to smem
        #pragma unroll
        for (int j = 0; j < 4; j++) {
            int qg = q0 + ty * 4 + j;
            #pragma unroll
            for (int i = 0; i < 4; i++) {
                int kg = k0 + tx * 4 + i;
                float ww;
                if (diag && kg > qg) {
                    ww = 0.f;
                } else {
                    float d2 = fmaxf(q2r[j] + k2r[i] - 2.f * qk[j][i], 0.f);
                    float arg = fmaf(2.f * d2, rqr[j] * rkr[i], 1.f);
                    arg = fmaxf(arg, 1.f + 1e-7f);
                    float dist = __logf(arg + sqrtf((arg - 1.f) * (arg + 1.f)));
                    ww = __expf(-tau * dist - gamma);
                }
                float wl = ww * lvr[i];
                wS[(ty * 4 + j) * TPAD + tx * 4 + i] = wl;
                den[j] += wl - ww;  // = w*(lamv-1)
            }
        }
        __syncthreads();

        // phase 2: num += W_l . V
        #pragma unroll 4
        for (int kk = 0; kk < 64; kk += 4) {
            float4 w0 = *(const float4*)(&wS[(ty * 4 + 0) * TPAD + kk]);
            float4 w1 = *(const float4*)(&wS[(ty * 4 + 1) * TPAD + kk]);
            float4 w2 = *(const float4*)(&wS[(ty * 4 + 2) * TPAD + kk]);
            float4 w3 = *(const float4*)(&wS[(ty * 4 + 3) * TPAD + kk]);
            float wa[4][4] = {{w0.x, w0.y, w0.z, w0.w}, {w1.x, w1.y, w1.z, w1.w},
                              {w2.x, w2.y, w2.z, w2.w}, {w3.x, w3.y, w3.z, w3.w}};
            #pragma unroll
            for (int c = 0; c < 4; c++) {
                float4 b4 = *(const float4*)(&vS[(kk + c) * TPAD + tx * 4]);
                float bb[4] = {b4.x, b4.y, b4.z, b4.w};
                #pragma unroll
                for (int j = 0; j < 4; j++)
                    #pragma unroll
                    for (int i = 0; i < 4; i++) num[j][i] = fmaf(wa[j][c], bb[i], num[j][i]);
            }
        }
        __syncthreads();
    }

    // epilogue: reduce den & ||g|| across the 16 tx lanes, Mobius half + beta-concat
    #pragma unroll
    for (int j = 0; j < 4; j++) {
        float d = den[j];
        #pragma unroll
        for (int m = 8; m; m >>= 1) d += __shfl_xor_sync(0xffffffffu, d, m);
        d = fmaxf(d, EPSF);
        float inv = 1.f / d;
        float g[4];
        float gs = 0.f;
        #pragma unroll
        for (int i = 0; i < 4; i++) { g[i] = num[j][i] * inv; gs += g[i] * g[i]; }
        #pragma unroll
        for (int m = 8; m; m >>= 1) gs += __shfl_xor_sync(0xffffffffu, gs, m);
        float gn = fmaxf(sqrtf(gs), EPSF);
        float xc = fminf(gn, 1.f - 1e-7f);
        float tt = xc / (1.f + sqrtf(1.f - xc * xc));  // tanh(0.5*atanh(xc))
        float f = beta * tt / gn;
        int qg = q0 + ty * 4 + j;
        #pragma unroll
        for (int i = 0; i < 4; i++)
            out[(size_t)qg * EM + h * HD + tx * 4 + i] = f * g[i];
    }
}

// ---------------- launch ----------------
extern "C" void kernel_launch(void* const* d_in, const int* in_sizes, int n_in,
                              void* d_out, int out_size) {
    const float* q  = (const float*)d_in[0];
    const float* k  = (const float*)d_in[1];
    const float* v  = (const float*)d_in[2];
    const float* Wq = (const float*)d_in[3];
    const float* Wk = (const float*)d_in[4];
    const float* Wv = (const float*)d_in[5];
    const float* bq = (const float*)d_in[6];
    const float* bk = (const float*)d_in[7];
    const float* bv = (const float*)d_in[8];
    const float* st = (const float*)d_in[9];
    const float* sg = (const float*)d_in[10];
    float* out = (float*)d_out;

    // beta(E/2,1/2) / beta(hd/2,1/2) via lgamma (host)
    double lb = (lgamma(256.0) + lgamma(0.5) - lgamma(256.5))
              - (lgamma(32.0) + lgamma(0.5) - lgamma(32.5));
    float beta = (float)exp(lb);

    cudaFuncSetAttribute(attn_k, cudaFuncAttributeMaxDynamicSharedMemorySize,
                         ATTN_SMEM_FLOATS * (int)sizeof(float));

    colnorm_k<<<dim3(2, 3), 256>>>(Wq, Wk, Wv, bq, bk, bv);
    rownorm_k<<<dim3(SQ, 3), 32>>>(q, k, v);
    proj_k<<<dim3(EM / 64, SQ / 64, 3), 256>>>(q, k, v, Wq, Wk, Wv);
    normaux_k<<<dim3(SQ, 3), 128>>>();
    transpose_k<<<dim3(EM / 32, SQ / 32, 2), dim3(32, 8)>>>();
    attn_k<<<(SQ / 64) * NH, 256, ATTN_SMEM_FLOATS * (int)sizeof(float)>>>(st, sg, beta, out);
    (void)in_sizes; (void)n_in; (void)out_size;
}

// round 10
// speedup vs baseline: 1.9677x; 1.2521x over previous
#include <cuda_runtime.h>
#include <cuda_bf16.h>
#include <stdint.h>
#include <math.h>

#define SQ 2048
#define EM 512
#define NH 8
#define HD 64
#define EPSF 1e-15f

// ---------------- scratch (static device globals; no allocation) ----------------
__device__ float g_proj[3][SQ * EM];            // projected+normalized q/k/v points, [S][E]
__device__ __nv_bfloat16 g_bf[2][SQ * EM];      // bf16 copies of q,k points for MMA
__device__ float g_x2[3][SQ];
__device__ float g_zn[3][EM];
__device__ float g_chv[3][EM];
__device__ float g_shv[3][EM];
__device__ float g_pt2[3][NH * SQ];
__device__ float g_rinv[3][NH * SQ];

// ---------------- mma helpers ----------------
__device__ __forceinline__ uint32_t smem_u32(const void* p) {
    return (uint32_t)__cvta_generic_to_shared(p);
}
__device__ __forceinline__ void ldsm4(uint32_t& a0, uint32_t& a1, uint32_t& a2, uint32_t& a3,
                                      uint32_t addr) {
    asm volatile("ldmatrix.sync.aligned.m8n8.x4.shared.b16 {%0,%1,%2,%3}, [%4];"
                 : "=r"(a0), "=r"(a1), "=r"(a2), "=r"(a3) : "r"(addr));
}
__device__ __forceinline__ void ldsm2(uint32_t& b0, uint32_t& b1, uint32_t addr) {
    asm volatile("ldmatrix.sync.aligned.m8n8.x2.shared.b16 {%0,%1}, [%2];"
                 : "=r"(b0), "=r"(b1) : "r"(addr));
}
__device__ __forceinline__ void mma16816(float* c, uint32_t a0, uint32_t a1, uint32_t a2,
                                         uint32_t a3, uint32_t b0, uint32_t b1) {
    asm volatile(
        "mma.sync.aligned.m16n8k16.row.col.f32.bf16.bf16.f32 "
        "{%0,%1,%2,%3}, {%4,%5,%6,%7}, {%8,%9}, {%0,%1,%2,%3};"
        : "+f"(c[0]), "+f"(c[1]), "+f"(c[2]), "+f"(c[3])
        : "r"(a0), "r"(a1), "r"(a2), "r"(a3), "r"(b0), "r"(b1));
}

// ---------------- kernel 1: W column norms + bias cosh/sinh ----------------
__global__ void colnorm_k(const float* __restrict__ W0, const float* __restrict__ W1,
                          const float* __restrict__ W2, const float* __restrict__ b0,
                          const float* __restrict__ b1, const float* __restrict__ b2) {
    int t = blockIdx.y;
    int j = blockIdx.x * blockDim.x + threadIdx.x;
    if (j >= EM) return;
    const float* W = (t == 0) ? W0 : ((t == 1) ? W1 : W2);
    const float* b = (t == 0) ? b0 : ((t == 1) ? b1 : b2);
    float s = 0.f;
    for (int i = 0; i < EM; i++) { float v = W[i * EM + j]; s = fmaf(v, v, s); }
    float zn = fmaxf(sqrtf(s), EPSF);
    float r2 = 2.f * b[j];
    g_zn[t][j] = zn;
    g_chv[t][j] = coshf(r2);
    g_shv[t][j] = sinhf(r2);
}

// ---------------- kernel 2: per-token input squared norms ----------------
__global__ void rownorm_k(const float* __restrict__ x0, const float* __restrict__ x1,
                          const float* __restrict__ x2) {
    int t = blockIdx.y, s = blockIdx.x, lane = threadIdx.x;
    const float* x = (t == 0) ? x0 : ((t == 1) ? x1 : x2);
    const float4* row = (const float4*)(x + (size_t)s * EM);
    float acc = 0.f;
    for (int i = lane; i < EM / 4; i += 32) {
        float4 v = row[i];
        acc += v.x * v.x + v.y * v.y + v.z * v.z + v.w * v.w;
    }
    #pragma unroll
    for (int m = 16; m; m >>= 1) acc += __shfl_xor_sync(0xffffffffu, acc, m);
    if (lane == 0) g_x2[t][s] = acc;
}

// ---------------- kernel 3: projection GEMM + fast h_linear epilogue ----------------
__global__ __launch_bounds__(256) void proj_k(
    const float* __restrict__ x0, const float* __restrict__ x1, const float* __restrict__ x2,
    const float* __restrict__ W0, const float* __restrict__ W1, const float* __restrict__ W2) {
    int t = blockIdx.z;
    const float* X = (t == 0) ? x0 : ((t == 1) ? x1 : x2);
    const float* W = (t == 0) ? W0 : ((t == 1) ? W1 : W2);
    int n0 = blockIdx.x * 64, m0 = blockIdx.y * 64;
    __shared__ float aT[16][68];
    __shared__ float bS[16][68];
    int tid = threadIdx.x;
    int tx = tid & 15, ty = tid >> 4;
    float acc[4][4] = {};
    for (int k0 = 0; k0 < EM; k0 += 16) {
        {
            int m = tid >> 2, kb = (tid & 3) * 4;
            float4 v = *(const float4*)(X + (size_t)(m0 + m) * EM + k0 + kb);
            aT[kb + 0][m] = v.x; aT[kb + 1][m] = v.y; aT[kb + 2][m] = v.z; aT[kb + 3][m] = v.w;
            int kk = tid >> 4, nb = (tid & 15) * 4;
            *(float4*)(&bS[kk][nb]) = *(const float4*)(W + (size_t)(k0 + kk) * EM + n0 + nb);
        }
        __syncthreads();
        #pragma unroll
        for (int kk = 0; kk < 16; kk++) {
            float4 a4 = *(const float4*)(&aT[kk][ty * 4]);
            float4 b4 = *(const float4*)(&bS[kk][tx * 4]);
            float av[4] = {a4.x, a4.y, a4.z, a4.w};
            float bv[4] = {b4.x, b4.y, b4.z, b4.w};
            #pragma unroll
            for (int j = 0; j < 4; j++)
                #pragma unroll
                for (int i = 0; i < 4; i++) acc[j][i] = fmaf(av[j], bv[i], acc[j][i]);
        }
        __syncthreads();
    }
    int col_base = n0 + tx * 4;
    float znr[4], rzn[4], chr[4], shr[4];
    #pragma unroll
    for (int i = 0; i < 4; i++) {
        znr[i] = g_zn[t][col_base + i];
        rzn[i] = 1.f / znr[i];
        chr[i] = g_chv[t][col_base + i];
        shr[i] = g_shv[t][col_base + i];
    }
    #pragma unroll
    for (int j = 0; j < 4; j++) {
        int row = m0 + ty * 4 + j;
        float x2 = g_x2[t][row];
        float lam = 2.f / (1.f - x2);
        #pragma unroll
        for (int i = 0; i < 4; i++) {
            float arg = (acc[j][i] * lam * rzn[i]) * chr[i] - (lam - 1.f) * shr[i];
            float as = __logf(arg + sqrtf(fmaf(arg, arg, 1.f)));   // asinh
            float dd = 2.f * znr[i] * as;
            float e = __expf(dd);
            g_proj[t][(size_t)row * EM + col_base + i] = 0.5f * (e - 1.f / e);  // sinh
        }
    }
}

// ---------------- kernel 4: ball normalization + per-head aux + bf16 copies ----------------
__global__ void normaux_k() {
    int t = blockIdx.y, s = blockIdx.x, tid = threadIdx.x;  // 128 threads
    float* row = &g_proj[t][(size_t)s * EM];
    float4 v = ((float4*)row)[tid];
    float l4 = v.x * v.x + v.y * v.y + v.z * v.z + v.w * v.w;
    float tot = l4;
    #pragma unroll
    for (int m = 16; m; m >>= 1) tot += __shfl_xor_sync(0xffffffffu, tot, m);
    __shared__ float wsum[4];
    if ((tid & 31) == 0) wsum[tid >> 5] = tot;
    __syncthreads();
    float total = wsum[0] + wsum[1] + wsum[2] + wsum[3];
    float scale = 1.f / (1.f + sqrtf(1.f + total));
    v.x *= scale; v.y *= scale; v.z *= scale; v.w *= scale;
    ((float4*)row)[tid] = v;
    if (t < 2) {
        __nv_bfloat16* bdst = &g_bf[t][(size_t)s * EM + tid * 4];
        bdst[0] = __float2bfloat16(v.x);
        bdst[1] = __float2bfloat16(v.y);
        bdst[2] = __float2bfloat16(v.z);
        bdst[3] = __float2bfloat16(v.w);
    }
    float hs = l4;
    #pragma unroll
    for (int m = 8; m; m >>= 1) hs += __shfl_xor_sync(0xffffffffu, hs, m);
    if ((tid & 15) == 0) {
        int h = tid >> 4;
        float pt2 = scale * scale * hs;
        g_pt2[t][h * SQ + s] = pt2;
        g_rinv[t][h * SQ + s] = 1.f / (1.f - pt2);
    }
}

// ---------------- kernel 5: causal hyperbolic attention ----------------
// smem layout (bytes): qB bf16 64x72 @0 (9216), kB @9216, vS f32 64x68 @18432 (17408),
// wS @35840 (17408), q2s@53248, rqs@53504, k2s@53760, rks@54016, lvs@54272, denP[2][64]@54528
#define ATTN_SMEM_BYTES 55040
#define TPAD 68
#define BROW 144   // bf16 tile row stride in bytes (72 bf16)

__device__ __forceinline__ float wfun(float qk, float q2, float rq, float k2, float rk,
                                      int qg, int kg, float tau, float gamma) {
    if (kg > qg) return 0.f;
    float d2 = fmaxf(q2 + k2 - 2.f * qk, 0.f);
    float arg = fmaf(2.f * d2, rq * rk, 1.f);
    arg = fmaxf(arg, 1.f + 1e-7f);
    float dist = __logf(arg + sqrtf((arg - 1.f) * (arg + 1.f)));
    return __expf(-tau * dist - gamma);
}

__global__ __launch_bounds__(256) void attn_k(const float* __restrict__ stau,
                                              const float* __restrict__ sgam,
                                              float beta, float* __restrict__ out) {
    int bid = blockIdx.x;
    int h = bid & (NH - 1);
    int qt = (SQ / 64 - 1) - (bid >> 3);
    int q0 = qt * 64;
    extern __shared__ char sraw[];
    __nv_bfloat16* qB = (__nv_bfloat16*)sraw;
    __nv_bfloat16* kB = (__nv_bfloat16*)(sraw + 9216);
    float* vS  = (float*)(sraw + 18432);
    float* wS  = (float*)(sraw + 35840);
    float* q2s = (float*)(sraw + 53248);
    float* rqs = (float*)(sraw + 53504);
    float* k2s = (float*)(sraw + 53760);
    float* rks = (float*)(sraw + 54016);
    float* lvs = (float*)(sraw + 54272);
    float* denP = (float*)(sraw + 54528);  // [2][64]

    int tid = threadIdx.x, tx = tid & 15, ty = tid >> 4;
    int l = tid & 31, w = tid >> 5;
    int wq0 = (w >> 1) << 4;   // 0,16,32,48
    int wk0 = (w & 1) << 5;    // 0,32
    float tau = __expf(stau[0]);
    float gamma = sgam[0];

    // ldmatrix base addresses
    uint32_t qBb = smem_u32(qB), kBb = smem_u32(kB);
    uint32_t aAddrBase = qBb + (uint32_t)(wq0 + (l & 15)) * BROW + (uint32_t)((l >> 4) << 3) * 2;
    uint32_t bAddrBase = kBb + (uint32_t)(l & 7) * BROW + (uint32_t)(l & 8) * 2;

    // load q tile (bf16) + q aux
    {
        #pragma unroll
        for (int p = 0; p < 2; p++) {
            int idx = tid + 256 * p;
            int row = idx >> 3, c8 = (idx & 7) * 8;
            *(uint4*)((char*)qB + row * BROW + c8 * 2) =
                *(const uint4*)(&g_bf[0][(size_t)(q0 + row) * EM + h * HD + c8]);
        }
        if (tid < 64) {
            q2s[tid] = g_pt2[0][h * SQ + q0 + tid];
            rqs[tid] = g_rinv[0][h * SQ + q0 + tid];
        }
    }
    __syncthreads();

    // per-lane fragment q-aux (rows r0, r0+8)
    int r0 = wq0 + (l >> 2), r1 = r0 + 8;
    float q2a0 = q2s[r0], rqa0 = rqs[r0];
    float q2a1 = q2s[r1], rqa1 = rqs[r1];
    int qg0 = q0 + r0, qg1 = q0 + r1;

    float num[4][4] = {};
    float den2_0 = 0.f, den2_1 = 0.f;

    for (int kt = 0; kt <= qt; kt++) {
        int k0 = kt * 64;
        {   // load k tile (bf16), v tile (fp32) + per-key aux
            #pragma unroll
            for (int p = 0; p < 2; p++) {
                int idx = tid + 256 * p;
                int row = idx >> 3, c8 = (idx & 7) * 8;
                *(uint4*)((char*)kB + row * BROW + c8 * 2) =
                    *(const uint4*)(&g_bf[1][(size_t)(k0 + row) * EM + h * HD + c8]);
            }
            const float* vsrc = &g_proj[2][(size_t)k0 * EM + h * HD];
            #pragma unroll
            for (int p = 0; p < 2; p++) {
                int R = (tid >> 3) + 32 * p;
                int c8 = (tid & 7) * 8;
                *(float4*)(&vS[R * TPAD + c8])     = *(const float4*)(vsrc + (size_t)R * EM + c8);
                *(float4*)(&vS[R * TPAD + c8 + 4]) = *(const float4*)(vsrc + (size_t)R * EM + c8 + 4);
            }
            if (tid < 64) {
                k2s[tid] = g_pt2[1][h * SQ + k0 + tid];
                rks[tid] = g_rinv[1][h * SQ + k0 + tid];
                lvs[tid] = 2.f * g_rinv[2][h * SQ + k0 + tid];
            }
        }
        __syncthreads();

        // phase 1: S = Q.K^T via bf16 mma (warp tile 16q x 32k, k-dim hd=64)
        float sc[4][4];
        #pragma unroll
        for (int nb = 0; nb < 4; nb++)
            #pragma unroll
            for (int i = 0; i < 4; i++) sc[nb][i] = 0.f;
        #pragma unroll
        for (int kc = 0; kc < 4; kc++) {
            uint32_t a0, a1, a2, a3;
            ldsm4(a0, a1, a2, a3, aAddrBase + kc * 32);
            #pragma unroll
            for (int nb = 0; nb < 4; nb++) {
                uint32_t b0, b1;
                ldsm2(b0, b1, bAddrBase + (uint32_t)(wk0 + nb * 8) * BROW + kc * 32);
                mma16816(sc[nb], a0, a1, a2, a3, b0, b1);
            }
        }

        // transform fragments -> w*lamv into wS (fp32), accumulate den
        #pragma unroll
        for (int nb = 0; nb < 4; nb++) {
            int colb = wk0 + nb * 8 + ((l & 3) << 1);
            float2 k2p = *(float2*)&k2s[colb];
            float2 rkp = *(float2*)&rks[colb];
            float2 lvp = *(float2*)&lvs[colb];
            int kg = k0 + colb;
            float w00 = wfun(sc[nb][0], q2a0, rqa0, k2p.x, rkp.x, qg0, kg,     tau, gamma);
            float w01 = wfun(sc[nb][1], q2a0, rqa0, k2p.y, rkp.y, qg0, kg + 1, tau, gamma);
            float w10 = wfun(sc[nb][2], q2a1, rqa1, k2p.x, rkp.x, qg1, kg,     tau, gamma);
            float w11 = wfun(sc[nb][3], q2a1, rqa1, k2p.y, rkp.y, qg1, kg + 1, tau, gamma);
            float wl00 = w00 * lvp.x, wl01 = w01 * lvp.y;
            float wl10 = w10 * lvp.x, wl11 = w11 * lvp.y;
            *(float2*)&wS[r0 * TPAD + colb] = make_float2(wl00, wl01);
            *(float2*)&wS[r1 * TPAD + colb] = make_float2(wl10, wl11);
            den2_0 += (wl00 - w00) + (wl01 - w01);
            den2_1 += (wl10 - w10) + (wl11 - w11);
        }
        __syncthreads();

        // phase 2: num += W_l . V  (SIMT fp32, 4x4 microtile)
        #pragma unroll 4
        for (int kk = 0; kk < 64; kk += 4) {
            float4 w0 = *(const float4*)(&wS[(ty * 4 + 0) * TPAD + kk]);
            float4 w1 = *(const float4*)(&wS[(ty * 4 + 1) * TPAD + kk]);
            float4 w2 = *(const float4*)(&wS[(ty * 4 + 2) * TPAD + kk]);
            float4 w3 = *(const float4*)(&wS[(ty * 4 + 3) * TPAD + kk]);
            float wa[4][4] = {{w0.x, w0.y, w0.z, w0.w}, {w1.x, w1.y, w1.z, w1.w},
                              {w2.x, w2.y, w2.z, w2.w}, {w3.x, w3.y, w3.z, w3.w}};
            #pragma unroll
            for (int c = 0; c < 4; c++) {
                float4 b4 = *(const float4*)(&vS[(kk + c) * TPAD + tx * 4]);
                float bb[4] = {b4.x, b4.y, b4.z, b4.w};
                #pragma unroll
                for (int j = 0; j < 4; j++)
                    #pragma unroll
                    for (int i = 0; i < 4; i++) num[j][i] = fmaf(wa[j][c], bb[i], num[j][i]);
            }
        }
        __syncthreads();
    }

    // fold den partials: reduce over the 4 lanes sharing rows, stage per k-half
    den2_0 += __shfl_xor_sync(0xffffffffu, den2_0, 1);
    den2_0 += __shfl_xor_sync(0xffffffffu, den2_0, 2);
    den2_1 += __shfl_xor_sync(0xffffffffu, den2_1, 1);
    den2_1 += __shfl_xor_sync(0xffffffffu, den2_1, 2);
    if ((l & 3) == 0) {
        denP[(w & 1) * 64 + r0] = den2_0;
        denP[(w & 1) * 64 + r1] = den2_1;
    }
    __syncthreads();

    // epilogue: Mobius half + beta-concat
    #pragma unroll
    for (int j = 0; j < 4; j++) {
        int qrow = ty * 4 + j;
        float d = fmaxf(denP[qrow] + denP[64 + qrow], EPSF);
        float inv = 1.f / d;
        float g[4];
        float gs = 0.f;
        #pragma unroll
        for (int i = 0; i < 4; i++) { g[i] = num[j][i] * inv; gs += g[i] * g[i]; }
        #pragma unroll
        for (int m = 8; m; m >>= 1) gs += __shfl_xor_sync(0xffffffffu, gs, m);
        float gn = fmaxf(sqrtf(gs), EPSF);
        float xc = fminf(gn, 1.f - 1e-7f);
        float tt = xc / (1.f + sqrtf(1.f - xc * xc));  // tanh(0.5*atanh(xc))
        float f = beta * tt / gn;
        int qg = q0 + qrow;
        #pragma unroll
        for (int i = 0; i < 4; i++)
            out[(size_t)qg * EM + h * HD + tx * 4 + i] = f * g[i];
    }
}

// ---------------- launch ----------------
extern "C" void kernel_launch(void* const* d_in, const int* in_sizes, int n_in,
                              void* d_out, int out_size) {
    const float* q  = (const float*)d_in[0];
    const float* k  = (const float*)d_in[1];
    const float* v  = (const float*)d_in[2];
    const float* Wq = (const float*)d_in[3];
    const float* Wk = (const float*)d_in[4];
    const float* Wv = (const float*)d_in[5];
    const float* bq = (const float*)d_in[6];
    const float* bk = (const float*)d_in[7];
    const float* bv = (const float*)d_in[8];
    const float* st = (const float*)d_in[9];
    const float* sg = (const float*)d_in[10];
    float* out = (float*)d_out;

    double lb = (lgamma(256.0) + lgamma(0.5) - lgamma(256.5))
              - (lgamma(32.0) + lgamma(0.5) - lgamma(32.5));
    float beta = (float)exp(lb);

    cudaFuncSetAttribute(attn_k, cudaFuncAttributeMaxDynamicSharedMemorySize, ATTN_SMEM_BYTES);

    colnorm_k<<<dim3(2, 3), 256>>>(Wq, Wk, Wv, bq, bk, bv);
    rownorm_k<<<dim3(SQ, 3), 32>>>(q, k, v);
    proj_k<<<dim3(EM / 64, SQ / 64, 3), 256>>>(q, k, v, Wq, Wk, Wv);
    normaux_k<<<dim3(SQ, 3), 128>>>();
    attn_k<<<(SQ / 64) * NH, 256, ATTN_SMEM_BYTES>>>(st, sg, beta, out);
    (void)in_sizes; (void)n_in; (void)out_size;
}

// round 12
// speedup vs baseline: 2.4530x; 1.2466x over previous
#include <cuda_runtime.h>
#include <cuda_bf16.h>
#include <stdint.h>
#include <math.h>

#define SQ 2048
#define EM 512
#define NH 8
#define HD 64
#define EPSF 1e-15f

// ---------------- scratch (static device globals; no allocation) ----------------
__device__ float g_proj[3][SQ * EM];            // projected+normalized q/k/v points, [S][E]
__device__ __nv_bfloat16 g_bf[2][SQ * EM];      // bf16 copies of q,k points for MMA
__device__ __nv_bfloat16 g_vhi[SQ * EM];        // v split: hi part
__device__ __nv_bfloat16 g_vlo[SQ * EM];        // v split: lo part
__device__ float g_x2[3][SQ];
__device__ float g_zn[3][EM];
__device__ float g_chv[3][EM];
__device__ float g_shv[3][EM];
__device__ float g_pt2[3][NH * SQ];
__device__ float g_rinv[3][NH * SQ];

// ---------------- mma helpers ----------------
__device__ __forceinline__ uint32_t smem_u32(const void* p) {
    return (uint32_t)__cvta_generic_to_shared(p);
}
__device__ __forceinline__ void ldsm4(uint32_t& a0, uint32_t& a1, uint32_t& a2, uint32_t& a3,
                                      uint32_t addr) {
    asm volatile("ldmatrix.sync.aligned.m8n8.x4.shared.b16 {%0,%1,%2,%3}, [%4];"
                 : "=r"(a0), "=r"(a1), "=r"(a2), "=r"(a3) : "r"(addr));
}
__device__ __forceinline__ void ldsm2(uint32_t& b0, uint32_t& b1, uint32_t addr) {
    asm volatile("ldmatrix.sync.aligned.m8n8.x2.shared.b16 {%0,%1}, [%2];"
                 : "=r"(b0), "=r"(b1) : "r"(addr));
}
__device__ __forceinline__ void ldsm2t(uint32_t& b0, uint32_t& b1, uint32_t addr) {
    asm volatile("ldmatrix.sync.aligned.m8n8.x2.trans.shared.b16 {%0,%1}, [%2];"
                 : "=r"(b0), "=r"(b1) : "r"(addr));
}
__device__ __forceinline__ void mma16816(float* c, uint32_t a0, uint32_t a1, uint32_t a2,
                                         uint32_t a3, uint32_t b0, uint32_t b1) {
    asm volatile(
        "mma.sync.aligned.m16n8k16.row.col.f32.bf16.bf16.f32 "
        "{%0,%1,%2,%3}, {%4,%5,%6,%7}, {%8,%9}, {%0,%1,%2,%3};"
        : "+f"(c[0]), "+f"(c[1]), "+f"(c[2]), "+f"(c[3])
        : "r"(a0), "r"(a1), "r"(a2), "r"(a3), "r"(b0), "r"(b1));
}
__device__ __forceinline__ uint32_t packbf(__nv_bfloat16 a, __nv_bfloat16 b) {
    __nv_bfloat162 t; t.x = a; t.y = b;
    return *(uint32_t*)&t;
}

// ---------------- kernel 1: W column norms + bias cosh/sinh ----------------
__global__ void colnorm_k(const float* __restrict__ W0, const float* __restrict__ W1,
                          const float* __restrict__ W2, const float* __restrict__ b0,
                          const float* __restrict__ b1, const float* __restrict__ b2) {
    int t = blockIdx.y;
    int j = blockIdx.x * blockDim.x + threadIdx.x;
    if (j >= EM) return;
    const float* W = (t == 0) ? W0 : ((t == 1) ? W1 : W2);
    const float* b = (t == 0) ? b0 : ((t == 1) ? b1 : b2);
    float s = 0.f;
    for (int i = 0; i < EM; i++) { float v = W[i * EM + j]; s = fmaf(v, v, s); }
    float zn = fmaxf(sqrtf(s), EPSF);
    float r2 = 2.f * b[j];
    g_zn[t][j] = zn;
    g_chv[t][j] = coshf(r2);
    g_shv[t][j] = sinhf(r2);
}

// ---------------- kernel 2: per-token input squared norms ----------------
__global__ void rownorm_k(const float* __restrict__ x0, const float* __restrict__ x1,
                          const float* __restrict__ x2) {
    int t = blockIdx.y, s = blockIdx.x, lane = threadIdx.x;
    const float* x = (t == 0) ? x0 : ((t == 1) ? x1 : x2);
    const float4* row = (const float4*)(x + (size_t)s * EM);
    float acc = 0.f;
    for (int i = lane; i < EM / 4; i += 32) {
        float4 v = row[i];
        acc += v.x * v.x + v.y * v.y + v.z * v.z + v.w * v.w;
    }
    #pragma unroll
    for (int m = 16; m; m >>= 1) acc += __shfl_xor_sync(0xffffffffu, acc, m);
    if (lane == 0) g_x2[t][s] = acc;
}

// ---------------- kernel 3: projection GEMM + fast h_linear epilogue ----------------
__global__ __launch_bounds__(256) void proj_k(
    const float* __restrict__ x0, const float* __restrict__ x1, const float* __restrict__ x2,
    const float* __restrict__ W0, const float* __restrict__ W1, const float* __restrict__ W2) {
    int t = blockIdx.z;
    const float* X = (t == 0) ? x0 : ((t == 1) ? x1 : x2);
    const float* W = (t == 0) ? W0 : ((t == 1) ? W1 : W2);
    int n0 = blockIdx.x * 64, m0 = blockIdx.y * 64;
    __shared__ float aT[16][68];
    __shared__ float bS[16][68];
    int tid = threadIdx.x;
    int tx = tid & 15, ty = tid >> 4;
    float acc[4][4] = {};
    for (int k0 = 0; k0 < EM; k0 += 16) {
        {
            int m = tid >> 2, kb = (tid & 3) * 4;
            float4 v = *(const float4*)(X + (size_t)(m0 + m) * EM + k0 + kb);
            aT[kb + 0][m] = v.x; aT[kb + 1][m] = v.y; aT[kb + 2][m] = v.z; aT[kb + 3][m] = v.w;
            int kk = tid >> 4, nb = (tid & 15) * 4;
            *(float4*)(&bS[kk][nb]) = *(const float4*)(W + (size_t)(k0 + kk) * EM + n0 + nb);
        }
        __syncthreads();
        #pragma unroll
        for (int kk = 0; kk < 16; kk++) {
            float4 a4 = *(const float4*)(&aT[kk][ty * 4]);
            float4 b4 = *(const float4*)(&bS[kk][tx * 4]);
            float av[4] = {a4.x, a4.y, a4.z, a4.w};
            float bv[4] = {b4.x, b4.y, b4.z, b4.w};
            #pragma unroll
            for (int j = 0; j < 4; j++)
                #pragma unroll
                for (int i = 0; i < 4; i++) acc[j][i] = fmaf(av[j], bv[i], acc[j][i]);
        }
        __syncthreads();
    }
    int col_base = n0 + tx * 4;
    float znr[4], rzn[4], chr[4], shr[4];
    #pragma unroll
    for (int i = 0; i < 4; i++) {
        znr[i] = g_zn[t][col_base + i];
        rzn[i] = 1.f / znr[i];
        chr[i] = g_chv[t][col_base + i];
        shr[i] = g_shv[t][col_base + i];
    }
    #pragma unroll
    for (int j = 0; j < 4; j++) {
        int row = m0 + ty * 4 + j;
        float x2 = g_x2[t][row];
        float lam = 2.f / (1.f - x2);
        #pragma unroll
        for (int i = 0; i < 4; i++) {
            float arg = (acc[j][i] * lam * rzn[i]) * chr[i] - (lam - 1.f) * shr[i];
            float as = __logf(arg + sqrtf(fmaf(arg, arg, 1.f)));   // asinh
            float dd = 2.f * znr[i] * as;
            float e = __expf(dd);
            g_proj[t][(size_t)row * EM + col_base + i] = 0.5f * (e - 1.f / e);  // sinh
        }
    }
}

// ---------------- kernel 4: ball normalization + per-head aux + bf16 planes ----------------
__global__ void normaux_k() {
    int t = blockIdx.y, s = blockIdx.x, tid = threadIdx.x;  // 128 threads
    float* row = &g_proj[t][(size_t)s * EM];
    float4 v = ((float4*)row)[tid];
    float l4 = v.x * v.x + v.y * v.y + v.z * v.z + v.w * v.w;
    float tot = l4;
    #pragma unroll
    for (int m = 16; m; m >>= 1) tot += __shfl_xor_sync(0xffffffffu, tot, m);
    __shared__ float wsum[4];
    if ((tid & 31) == 0) wsum[tid >> 5] = tot;
    __syncthreads();
    float total = wsum[0] + wsum[1] + wsum[2] + wsum[3];
    float scale = 1.f / (1.f + sqrtf(1.f + total));
    v.x *= scale; v.y *= scale; v.z *= scale; v.w *= scale;
    ((float4*)row)[tid] = v;
    float vv[4] = {v.x, v.y, v.z, v.w};
    if (t < 2) {
        __nv_bfloat16* bdst = &g_bf[t][(size_t)s * EM + tid * 4];
        #pragma unroll
        for (int i = 0; i < 4; i++) bdst[i] = __float2bfloat16(vv[i]);
    } else {
        __nv_bfloat16* hdst = &g_vhi[(size_t)s * EM + tid * 4];
        __nv_bfloat16* ldst = &g_vlo[(size_t)s * EM + tid * 4];
        #pragma unroll
        for (int i = 0; i < 4; i++) {
            __nv_bfloat16 hi = __float2bfloat16(vv[i]);
            hdst[i] = hi;
            ldst[i] = __float2bfloat16(vv[i] - __bfloat162float(hi));
        }
    }
    float hs = l4;
    #pragma unroll
    for (int m = 8; m; m >>= 1) hs += __shfl_xor_sync(0xffffffffu, hs, m);
    if ((tid & 15) == 0) {
        int h = tid >> 4;
        float pt2 = scale * scale * hs;
        g_pt2[t][h * SQ + s] = pt2;
        g_rinv[t][h * SQ + s] = 1.f / (1.f - pt2);
    }
}

// ---------------- kernel 5: causal hyperbolic attention (full-MMA) ----------------
// smem (bytes): qB 64x72bf16 @0 (9216), kB @9216, vHi @18432, vLo @27648,
// q2s@36864, rqs@37120, k2s@37376, rks@37632, lvs@37888, denP[2][64]@38144..38656
// redS (f32 64x68, 17408B) overlays qB/kB after the k-loop.
#define ATTN_SMEM_BYTES 38656
#define BROW 144   // bf16 tile row stride in bytes (72 bf16)
#define RPAD 68

__device__ __forceinline__ float wfun(float qk, float q2, float rq, float k2, float rk,
                                      int qg, int kg, float tau, float gamma) {
    if (kg > qg) return 0.f;
    float d2 = fmaxf(q2 + k2 - 2.f * qk, 0.f);
    float arg = fmaf(2.f * d2, rq * rk, 1.f);
    arg = fmaxf(arg, 1.f + 1e-7f);
    float dist = __logf(arg + sqrtf((arg - 1.f) * (arg + 1.f)));
    return __expf(-tau * dist - gamma);
}

__global__ __launch_bounds__(256) void attn_k(const float* __restrict__ stau,
                                              const float* __restrict__ sgam,
                                              float beta, float* __restrict__ out) {
    int bid = blockIdx.x;
    int h = bid & (NH - 1);
    int qt = (SQ / 64 - 1) - (bid >> 3);
    int q0 = qt * 64;
    extern __shared__ char sraw[];
    __nv_bfloat16* qB = (__nv_bfloat16*)sraw;
    __nv_bfloat16* kB = (__nv_bfloat16*)(sraw + 9216);
    __nv_bfloat16* vH = (__nv_bfloat16*)(sraw + 18432);
    __nv_bfloat16* vL = (__nv_bfloat16*)(sraw + 27648);
    float* q2s = (float*)(sraw + 36864);
    float* rqs = (float*)(sraw + 37120);
    float* k2s = (float*)(sraw + 37376);
    float* rks = (float*)(sraw + 37632);
    float* lvs = (float*)(sraw + 37888);
    float* denP = (float*)(sraw + 38144);  // [2][64]

    int tid = threadIdx.x;
    int l = tid & 31, w = tid >> 5;
    int wq0 = (w >> 1) << 4;   // 0,16,32,48
    int wk0 = (w & 1) << 5;    // 0,32
    float tau = __expf(stau[0]);
    float gamma = sgam[0];

    uint32_t qBb = smem_u32(qB), kBb = smem_u32(kB);
    uint32_t vHb = smem_u32(vH), vLb = smem_u32(vL);
    uint32_t aAddrBase = qBb + (uint32_t)(wq0 + (l & 15)) * BROW + (uint32_t)((l >> 4) << 3) * 2;
    uint32_t bAddrBase = kBb + (uint32_t)(l & 7) * BROW + (uint32_t)(l & 8) * 2;
    uint32_t vRowOff = (uint32_t)(wk0 + (l & 15)) * BROW;

    // load q tile (bf16) + q aux
    {
        #pragma unroll
        for (int p = 0; p < 2; p++) {
            int idx = tid + 256 * p;
            int row = idx >> 3, c8 = (idx & 7) * 8;
            *(uint4*)((char*)qB + row * BROW + c8 * 2) =
                *(const uint4*)(&g_bf[0][(size_t)(q0 + row) * EM + h * HD + c8]);
        }
        if (tid < 64) {
            q2s[tid] = g_pt2[0][h * SQ + q0 + tid];
            rqs[tid] = g_rinv[0][h * SQ + q0 + tid];
        }
    }
    __syncthreads();

    int r0 = wq0 + (l >> 2), r1 = r0 + 8;
    float q2a0 = q2s[r0], rqa0 = rqs[r0];
    float q2a1 = q2s[r1], rqa1 = rqs[r1];
    int qg0 = q0 + r0, qg1 = q0 + r1;

    float Cn[8][4] = {};          // num accumulator, 16q x 64hd per warp (its key half)
    float den2_0 = 0.f, den2_1 = 0.f;

    for (int kt = 0; kt <= qt; kt++) {
        int k0 = kt * 64;
        {   // load k tile (bf16), v hi/lo tiles (bf16) + per-key aux
            #pragma unroll
            for (int p = 0; p < 2; p++) {
                int idx = tid + 256 * p;
                int row = idx >> 3, c8 = (idx & 7) * 8;
                size_t src = (size_t)(k0 + row) * EM + h * HD + c8;
                *(uint4*)((char*)kB + row * BROW + c8 * 2) = *(const uint4*)(&g_bf[1][src]);
                *(uint4*)((char*)vH + row * BROW + c8 * 2) = *(const uint4*)(&g_vhi[src]);
                *(uint4*)((char*)vL + row * BROW + c8 * 2) = *(const uint4*)(&g_vlo[src]);
            }
            if (tid < 64) {
                k2s[tid] = g_pt2[1][h * SQ + k0 + tid];
                rks[tid] = g_rinv[1][h * SQ + k0 + tid];
                lvs[tid] = 2.f * g_rinv[2][h * SQ + k0 + tid];
            }
        }
        __syncthreads();

        // phase 1: S = Q.K^T via bf16 mma (warp tile 16q x 32k over hd=64)
        float sc[4][4];
        #pragma unroll
        for (int nb = 0; nb < 4; nb++)
            #pragma unroll
            for (int i = 0; i < 4; i++) sc[nb][i] = 0.f;
        #pragma unroll
        for (int kc = 0; kc < 4; kc++) {
            uint32_t a0, a1, a2, a3;
            ldsm4(a0, a1, a2, a3, aAddrBase + kc * 32);
            #pragma unroll
            for (int nb = 0; nb < 4; nb++) {
                uint32_t b0, b1;
                ldsm2(b0, b1, bAddrBase + (uint32_t)(wk0 + nb * 8) * BROW + kc * 32);
                mma16816(sc[nb], a0, a1, a2, a3, b0, b1);
            }
        }

        // transform: distance -> exp weight -> wl split into bf16 A fragments
        float k2r0, rkr0, lvr0;
        uint32_t aHi[2][4], aLo[2][4];
        #pragma unroll
        for (int nb = 0; nb < 4; nb++) {
            int colb = wk0 + nb * 8 + ((l & 3) << 1);
            float2 k2p = *(float2*)&k2s[colb];
            float2 rkp = *(float2*)&rks[colb];
            float2 lvp = *(float2*)&lvs[colb];
            int kg = k0 + colb;
            float w00 = wfun(sc[nb][0], q2a0, rqa0, k2p.x, rkp.x, qg0, kg,     tau, gamma);
            float w01 = wfun(sc[nb][1], q2a0, rqa0, k2p.y, rkp.y, qg0, kg + 1, tau, gamma);
            float w10 = wfun(sc[nb][2], q2a1, rqa1, k2p.x, rkp.x, qg1, kg,     tau, gamma);
            float w11 = wfun(sc[nb][3], q2a1, rqa1, k2p.y, rkp.y, qg1, kg + 1, tau, gamma);
            float wl00 = w00 * lvp.x, wl01 = w01 * lvp.y;
            float wl10 = w10 * lvp.x, wl11 = w11 * lvp.y;
            den2_0 += (wl00 - w00) + (wl01 - w01);
            den2_1 += (wl10 - w10) + (wl11 - w11);
            __nv_bfloat16 h00 = __float2bfloat16(wl00), h01 = __float2bfloat16(wl01);
            __nv_bfloat16 h10 = __float2bfloat16(wl10), h11 = __float2bfloat16(wl11);
            __nv_bfloat16 e00 = __float2bfloat16(wl00 - __bfloat162float(h00));
            __nv_bfloat16 e01 = __float2bfloat16(wl01 - __bfloat162float(h01));
            __nv_bfloat16 e10 = __float2bfloat16(wl10 - __bfloat162float(h10));
            __nv_bfloat16 e11 = __float2bfloat16(wl11 - __bfloat162float(h11));
            int kc = nb >> 1, ri = (nb & 1) << 1;
            aHi[kc][ri + 0] = packbf(h00, h01);
            aHi[kc][ri + 1] = packbf(h10, h11);
            aLo[kc][ri + 0] = packbf(e00, e01);
            aLo[kc][ri + 1] = packbf(e10, e11);
        }
        (void)k2r0; (void)rkr0; (void)lvr0;

        // phase 2: num += W_l . V via mma (A = wl fragments, B = v hi/lo, 3-way split)
        #pragma unroll
        for (int kc = 0; kc < 2; kc++) {
            uint32_t rowAddrH = vHb + vRowOff + (uint32_t)(kc * 16) * BROW;
            uint32_t rowAddrL = vLb + vRowOff + (uint32_t)(kc * 16) * BROW;
            #pragma unroll
            for (int nt = 0; nt < 8; nt++) {
                uint32_t bh0, bh1, bl0, bl1;
                ldsm2t(bh0, bh1, rowAddrH + nt * 16);
                ldsm2t(bl0, bl1, rowAddrL + nt * 16);
                mma16816(Cn[nt], aHi[kc][0], aHi[kc][1], aHi[kc][2], aHi[kc][3], bh0, bh1);
                mma16816(Cn[nt], aHi[kc][0], aHi[kc][1], aHi[kc][2], aHi[kc][3], bl0, bl1);
                mma16816(Cn[nt], aLo[kc][0], aLo[kc][1], aLo[kc][2], aLo[kc][3], bh0, bh1);
            }
        }
        __syncthreads();
    }

    // fold den partials (quad lanes share rows), stage per key-half
    den2_0 += __shfl_xor_sync(0xffffffffu, den2_0, 1);
    den2_0 += __shfl_xor_sync(0xffffffffu, den2_0, 2);
    den2_1 += __shfl_xor_sync(0xffffffffu, den2_1, 1);
    den2_1 += __shfl_xor_sync(0xffffffffu, den2_1, 2);
    if ((l & 3) == 0) {
        denP[(w & 1) * 64 + r0] = den2_0;
        denP[(w & 1) * 64 + r1] = den2_1;
    }
    __syncthreads();

    // cross-warp num reduction: odd (wk0=32) warps stage, even warps add
    float* redS = (float*)sraw;  // 64 x RPAD, overlays qB/kB
    if (w & 1) {
        #pragma unroll
        for (int nt = 0; nt < 8; nt++) {
            int c = nt * 8 + ((l & 3) << 1);
            *(float2*)&redS[r0 * RPAD + c] = make_float2(Cn[nt][0], Cn[nt][1]);
            *(float2*)&redS[r1 * RPAD + c] = make_float2(Cn[nt][2], Cn[nt][3]);
        }
    }
    __syncthreads();
    if (!(w & 1)) {
        #pragma unroll
        for (int nt = 0; nt < 8; nt++) {
            int c = nt * 8 + ((l & 3) << 1);
            float2 p0 = *(float2*)&redS[r0 * RPAD + c];
            float2 p1 = *(float2*)&redS[r1 * RPAD + c];
            Cn[nt][0] += p0.x; Cn[nt][1] += p0.y;
            Cn[nt][2] += p1.x; Cn[nt][3] += p1.y;
        }
        // epilogue in fragment layout: rows r0, r1
        #pragma unroll
        for (int half = 0; half < 2; half++) {
            int r = half ? r1 : r0;
            float d = fmaxf(denP[r] + denP[64 + r], EPSF);
            float inv = 1.f / d;
            float gv[16];
            float gs = 0.f;
            #pragma unroll
            for (int nt = 0; nt < 8; nt++) {
                float g0 = Cn[nt][half * 2 + 0] * inv;
                float g1 = Cn[nt][half * 2 + 1] * inv;
                gv[nt * 2] = g0; gv[nt * 2 + 1] = g1;
                gs += g0 * g0 + g1 * g1;
            }
            gs += __shfl_xor_sync(0xffffffffu, gs, 1);
            gs += __shfl_xor_sync(0xffffffffu, gs, 2);
            float gn = fmaxf(sqrtf(gs), EPSF);
            float xc = fminf(gn, 1.f - 1e-7f);
            float tt = xc / (1.f + sqrtf(1.f - xc * xc));  // tanh(0.5*atanh(xc))
            float f = beta * tt / gn;
            float* orow = out + (size_t)(q0 + r) * EM + h * HD;
            #pragma unroll
            for (int nt = 0; nt < 8; nt++) {
                int c = nt * 8 + ((l & 3) << 1);
                *(float2*)&orow[c] = make_float2(f * gv[nt * 2], f * gv[nt * 2 + 1]);
            }
        }
    }
}

// ---------------- launch ----------------
extern "C" void kernel_launch(void* const* d_in, const int* in_sizes, int n_in,
                              void* d_out, int out_size) {
    const float* q  = (const float*)d_in[0];
    const float* k  = (const float*)d_in[1];
    const float* v  = (const float*)d_in[2];
    const float* Wq = (const float*)d_in[3];
    const float* Wk = (const float*)d_in[4];
    const float* Wv = (const float*)d_in[5];
    const float* bq = (const float*)d_in[6];
    const float* bk = (const float*)d_in[7];
    const float* bv = (const float*)d_in[8];
    const float* st = (const float*)d_in[9];
    const float* sg = (const float*)d_in[10];
    float* out = (float*)d_out;

    double lb = (lgamma(256.0) + lgamma(0.5) - lgamma(256.5))
              - (lgamma(32.0) + lgamma(0.5) - lgamma(32.5));
    float beta = (float)exp(lb);

    cudaFuncSetAttribute(attn_k, cudaFuncAttributeMaxDynamicSharedMemorySize, ATTN_SMEM_BYTES);

    colnorm_k<<<dim3(2, 3), 256>>>(Wq, Wk, Wv, bq, bk, bv);
    rownorm_k<<<dim3(SQ, 3), 32>>>(q, k, v);
    proj_k<<<dim3(EM / 64, SQ / 64, 3), 256>>>(q, k, v, Wq, Wk, Wv);
    normaux_k<<<dim3(SQ, 3), 128>>>();
    attn_k<<<(SQ / 64) * NH, 256, ATTN_SMEM_BYTES>>>(st, sg, beta, out);
    (void)in_sizes; (void)n_in; (void)out_size;
}

// round 13
// speedup vs baseline: 3.1280x; 1.2752x over previous
#include <cuda_runtime.h>
#include <cuda_bf16.h>
#include <stdint.h>
#include <math.h>

#define SQ 2048
#define EM 512
#define NH 8
#define HD 64
#define EPSF 1e-15f

// ---------------- scratch (static device globals; no allocation) ----------------
__device__ float g_proj[3][SQ * EM];            // projected+normalized q/k/v points, [S][E]
__device__ __nv_bfloat16 g_bf[2][SQ * EM];      // bf16 copies of q,k points for attn MMA
__device__ __nv_bfloat16 g_vhi[SQ * EM];        // v split: hi part
__device__ __nv_bfloat16 g_vlo[SQ * EM];        // v split: lo part
__device__ __nv_bfloat16 g_xhi[3][SQ * EM];     // input x split planes
__device__ __nv_bfloat16 g_xlo[3][SQ * EM];
__device__ __nv_bfloat16 g_whi[3][EM * EM];     // weight W split planes
__device__ __nv_bfloat16 g_wlo[3][EM * EM];
__device__ float g_x2[3][SQ];
__device__ float g_zn[3][EM];
__device__ float g_chv[3][EM];
__device__ float g_shv[3][EM];
__device__ float g_pt2[3][NH * SQ];
__device__ float g_rinv[3][NH * SQ];

// ---------------- mma helpers ----------------
__device__ __forceinline__ uint32_t smem_u32(const void* p) {
    return (uint32_t)__cvta_generic_to_shared(p);
}
__device__ __forceinline__ void ldsm4(uint32_t& a0, uint32_t& a1, uint32_t& a2, uint32_t& a3,
                                      uint32_t addr) {
    asm volatile("ldmatrix.sync.aligned.m8n8.x4.shared.b16 {%0,%1,%2,%3}, [%4];"
                 : "=r"(a0), "=r"(a1), "=r"(a2), "=r"(a3) : "r"(addr));
}
__device__ __forceinline__ void ldsm2(uint32_t& b0, uint32_t& b1, uint32_t addr) {
    asm volatile("ldmatrix.sync.aligned.m8n8.x2.shared.b16 {%0,%1}, [%2];"
                 : "=r"(b0), "=r"(b1) : "r"(addr));
}
__device__ __forceinline__ void ldsm2t(uint32_t& b0, uint32_t& b1, uint32_t addr) {
    asm volatile("ldmatrix.sync.aligned.m8n8.x2.trans.shared.b16 {%0,%1}, [%2];"
                 : "=r"(b0), "=r"(b1) : "r"(addr));
}
__device__ __forceinline__ void mma16816(float* c, uint32_t a0, uint32_t a1, uint32_t a2,
                                         uint32_t a3, uint32_t b0, uint32_t b1) {
    asm volatile(
        "mma.sync.aligned.m16n8k16.row.col.f32.bf16.bf16.f32 "
        "{%0,%1,%2,%3}, {%4,%5,%6,%7}, {%8,%9}, {%0,%1,%2,%3};"
        : "+f"(c[0]), "+f"(c[1]), "+f"(c[2]), "+f"(c[3])
        : "r"(a0), "r"(a1), "r"(a2), "r"(a3), "r"(b0), "r"(b1));
}
__device__ __forceinline__ uint32_t packbf(__nv_bfloat16 a, __nv_bfloat16 b) {
    __nv_bfloat162 t; t.x = a; t.y = b;
    return *(uint32_t*)&t;
}

// ---------------- kernel 1: W column norms + bias cosh/sinh ----------------
__global__ void colnorm_k(const float* __restrict__ W0, const float* __restrict__ W1,
                          const float* __restrict__ W2, const float* __restrict__ b0,
                          const float* __restrict__ b1, const float* __restrict__ b2) {
    int t = blockIdx.y;
    int j = blockIdx.x * blockDim.x + threadIdx.x;
    if (j >= EM) return;
    const float* W = (t == 0) ? W0 : ((t == 1) ? W1 : W2);
    const float* b = (t == 0) ? b0 : ((t == 1) ? b1 : b2);
    float s = 0.f;
    for (int i = 0; i < EM; i++) { float v = W[i * EM + j]; s = fmaf(v, v, s); }
    float zn = fmaxf(sqrtf(s), EPSF);
    float r2 = 2.f * b[j];
    g_zn[t][j] = zn;
    g_chv[t][j] = coshf(r2);
    g_shv[t][j] = sinhf(r2);
}

// ---------------- kernel 2a: split inputs to bf16 hi/lo + row sumsq ----------------
__global__ void splitx_k(const float* __restrict__ x0, const float* __restrict__ x1,
                         const float* __restrict__ x2) {
    int t = blockIdx.y, s = blockIdx.x, tid = threadIdx.x;  // 128 threads
    const float* x = (t == 0) ? x0 : ((t == 1) ? x1 : x2);
    float4 v = ((const float4*)(x + (size_t)s * EM))[tid];
    float vv[4] = {v.x, v.y, v.z, v.w};
    float acc = v.x * v.x + v.y * v.y + v.z * v.z + v.w * v.w;
    #pragma unroll
    for (int m = 16; m; m >>= 1) acc += __shfl_xor_sync(0xffffffffu, acc, m);
    __shared__ float wsum[4];
    if ((tid & 31) == 0) wsum[tid >> 5] = acc;
    __nv_bfloat16* hdst = &g_xhi[t][(size_t)s * EM + tid * 4];
    __nv_bfloat16* ldst = &g_xlo[t][(size_t)s * EM + tid * 4];
    #pragma unroll
    for (int i = 0; i < 4; i++) {
        __nv_bfloat16 hi = __float2bfloat16(vv[i]);
        hdst[i] = hi;
        ldst[i] = __float2bfloat16(vv[i] - __bfloat162float(hi));
    }
    __syncthreads();
    if (tid == 0) g_x2[t][s] = wsum[0] + wsum[1] + wsum[2] + wsum[3];
}

// ---------------- kernel 2b: split weights to bf16 hi/lo ----------------
__global__ void splitw_k(const float* __restrict__ W0, const float* __restrict__ W1,
                         const float* __restrict__ W2) {
    int t = blockIdx.y, r = blockIdx.x, tid = threadIdx.x;  // 128 threads
    const float* W = (t == 0) ? W0 : ((t == 1) ? W1 : W2);
    float4 v = ((const float4*)(W + (size_t)r * EM))[tid];
    float vv[4] = {v.x, v.y, v.z, v.w};
    __nv_bfloat16* hdst = &g_whi[t][(size_t)r * EM + tid * 4];
    __nv_bfloat16* ldst = &g_wlo[t][(size_t)r * EM + tid * 4];
    #pragma unroll
    for (int i = 0; i < 4; i++) {
        __nv_bfloat16 hi = __float2bfloat16(vv[i]);
        hdst[i] = hi;
        ldst[i] = __float2bfloat16(vv[i] - __bfloat162float(hi));
    }
}

// ---------------- kernel 3: projection GEMM via bf16 MMA (3-term split) ----------------
#define BROW 144   // bf16 tile row stride in bytes (72 bf16)

__global__ __launch_bounds__(256) void proj_mma_k() {
    int t = blockIdx.z;
    int n0 = blockIdx.x * 64, m0 = blockIdx.y * 64;
    __shared__ __align__(16) char xHs[64 * BROW];
    __shared__ __align__(16) char xLs[64 * BROW];
    __shared__ __align__(16) char wHs[64 * BROW];
    __shared__ __align__(16) char wLs[64 * BROW];
    int tid = threadIdx.x;
    int l = tid & 31, w = tid >> 5;
    int wq0 = (w >> 1) << 4;   // m offset: 0,16,32,48
    int wk0 = (w & 1) << 5;    // n offset: 0,32

    uint32_t xHb = smem_u32(xHs), xLb = smem_u32(xLs);
    uint32_t wHb = smem_u32(wHs), wLb = smem_u32(wLs);
    uint32_t aOff = (uint32_t)(wq0 + (l & 15)) * BROW + (uint32_t)((l >> 4) << 3) * 2;
    uint32_t bOff = (uint32_t)(l & 15) * BROW + (uint32_t)wk0 * 2;

    float C[4][4] = {};  // 4 n-frags of 16x8

    for (int k0 = 0; k0 < EM; k0 += 64) {
        #pragma unroll
        for (int p = 0; p < 2; p++) {
            int idx = tid + 256 * p;
            int row = idx >> 3, c8 = (idx & 7) * 8;
            size_t xsrc = (size_t)(m0 + row) * EM + k0 + c8;
            size_t wsrc = (size_t)(k0 + row) * EM + n0 + c8;
            *(uint4*)(xHs + row * BROW + c8 * 2) = *(const uint4*)(&g_xhi[t][xsrc]);
            *(uint4*)(xLs + row * BROW + c8 * 2) = *(const uint4*)(&g_xlo[t][xsrc]);
            *(uint4*)(wHs + row * BROW + c8 * 2) = *(const uint4*)(&g_whi[t][wsrc]);
            *(uint4*)(wLs + row * BROW + c8 * 2) = *(const uint4*)(&g_wlo[t][wsrc]);
        }
        __syncthreads();
        #pragma unroll
        for (int kc = 0; kc < 4; kc++) {
            uint32_t ah0, ah1, ah2, ah3, al0, al1, al2, al3;
            ldsm4(ah0, ah1, ah2, ah3, xHb + aOff + kc * 32);
            ldsm4(al0, al1, al2, al3, xLb + aOff + kc * 32);
            #pragma unroll
            for (int nt = 0; nt < 4; nt++) {
                uint32_t bh0, bh1, bl0, bl1;
                uint32_t bAddr = bOff + (uint32_t)(kc * 16) * BROW + nt * 16;
                ldsm2t(bh0, bh1, wHb + bAddr);
                ldsm2t(bl0, bl1, wLb + bAddr);
                mma16816(C[nt], ah0, ah1, ah2, ah3, bh0, bh1);
                mma16816(C[nt], ah0, ah1, ah2, ah3, bl0, bl1);
                mma16816(C[nt], al0, al1, al2, al3, bh0, bh1);
            }
        }
        __syncthreads();
    }

    // h_linear epilogue in fragment layout
    int r0 = wq0 + (l >> 2), r1 = r0 + 8;
    float lam0 = 2.f / (1.f - g_x2[t][m0 + r0]);
    float lam1 = 2.f / (1.f - g_x2[t][m0 + r1]);
    #pragma unroll
    for (int nt = 0; nt < 4; nt++) {
        int c = n0 + wk0 + nt * 8 + ((l & 3) << 1);
        float2 zn2 = *(float2*)&g_zn[t][c];
        float2 ch2 = *(float2*)&g_chv[t][c];
        float2 sh2 = *(float2*)&g_shv[t][c];
        float rzn0 = 1.f / zn2.x, rzn1 = 1.f / zn2.y;
        float vals[4] = {C[nt][0], C[nt][1], C[nt][2], C[nt][3]};
        float res[4];
        #pragma unroll
        for (int q = 0; q < 4; q++) {
            float lam = (q < 2) ? lam0 : lam1;
            float rzn = (q & 1) ? rzn1 : rzn0;
            float ch = (q & 1) ? ch2.y : ch2.x;
            float sh = (q & 1) ? sh2.y : sh2.x;
            float zn = (q & 1) ? zn2.y : zn2.x;
            float arg = (vals[q] * lam * rzn) * ch - (lam - 1.f) * sh;
            float as = __logf(arg + sqrtf(fmaf(arg, arg, 1.f)));   // asinh
            float dd = 2.f * zn * as;
            float e = __expf(dd);
            res[q] = 0.5f * (e - 1.f / e);                          // sinh
        }
        *(float2*)&g_proj[t][(size_t)(m0 + r0) * EM + c] = make_float2(res[0], res[1]);
        *(float2*)&g_proj[t][(size_t)(m0 + r1) * EM + c] = make_float2(res[2], res[3]);
    }
}

// ---------------- kernel 4: ball normalization + per-head aux + bf16 planes ----------------
__global__ void normaux_k() {
    int t = blockIdx.y, s = blockIdx.x, tid = threadIdx.x;  // 128 threads
    float* row = &g_proj[t][(size_t)s * EM];
    float4 v = ((float4*)row)[tid];
    float l4 = v.x * v.x + v.y * v.y + v.z * v.z + v.w * v.w;
    float tot = l4;
    #pragma unroll
    for (int m = 16; m; m >>= 1) tot += __shfl_xor_sync(0xffffffffu, tot, m);
    __shared__ float wsum[4];
    if ((tid & 31) == 0) wsum[tid >> 5] = tot;
    __syncthreads();
    float total = wsum[0] + wsum[1] + wsum[2] + wsum[3];
    float scale = 1.f / (1.f + sqrtf(1.f + total));
    v.x *= scale; v.y *= scale; v.z *= scale; v.w *= scale;
    ((float4*)row)[tid] = v;
    float vv[4] = {v.x, v.y, v.z, v.w};
    if (t < 2) {
        __nv_bfloat16* bdst = &g_bf[t][(size_t)s * EM + tid * 4];
        #pragma unroll
        for (int i = 0; i < 4; i++) bdst[i] = __float2bfloat16(vv[i]);
    } else {
        __nv_bfloat16* hdst = &g_vhi[(size_t)s * EM + tid * 4];
        __nv_bfloat16* ldst = &g_vlo[(size_t)s * EM + tid * 4];
        #pragma unroll
        for (int i = 0; i < 4; i++) {
            __nv_bfloat16 hi = __float2bfloat16(vv[i]);
            hdst[i] = hi;
            ldst[i] = __float2bfloat16(vv[i] - __bfloat162float(hi));
        }
    }
    float hs = l4;
    #pragma unroll
    for (int m = 8; m; m >>= 1) hs += __shfl_xor_sync(0xffffffffu, hs, m);
    if ((tid & 15) == 0) {
        int h = tid >> 4;
        float pt2 = scale * scale * hs;
        g_pt2[t][h * SQ + s] = pt2;
        g_rinv[t][h * SQ + s] = 1.f / (1.f - pt2);
    }
}

// ---------------- kernel 5: causal hyperbolic attention (full-MMA) ----------------
#define ATTN_SMEM_BYTES 38656
#define RPAD 68

__device__ __forceinline__ float wfun(float qk, float q2, float rq, float k2, float rk,
                                      int qg, int kg, float tau, float gamma) {
    if (kg > qg) return 0.f;
    float d2 = fmaxf(q2 + k2 - 2.f * qk, 0.f);
    float arg = fmaf(2.f * d2, rq * rk, 1.f);
    arg = fmaxf(arg, 1.f + 1e-7f);
    float dist = __logf(arg + sqrtf((arg - 1.f) * (arg + 1.f)));
    return __expf(-tau * dist - gamma);
}

__global__ __launch_bounds__(256) void attn_k(const float* __restrict__ stau,
                                              const float* __restrict__ sgam,
                                              float beta, float* __restrict__ out) {
    int bid = blockIdx.x;
    int h = bid & (NH - 1);
    int qt = (SQ / 64 - 1) - (bid >> 3);
    int q0 = qt * 64;
    extern __shared__ char sraw[];
    __nv_bfloat16* qB = (__nv_bfloat16*)sraw;
    __nv_bfloat16* kB = (__nv_bfloat16*)(sraw + 9216);
    __nv_bfloat16* vH = (__nv_bfloat16*)(sraw + 18432);
    __nv_bfloat16* vL = (__nv_bfloat16*)(sraw + 27648);
    float* q2s = (float*)(sraw + 36864);
    float* rqs = (float*)(sraw + 37120);
    float* k2s = (float*)(sraw + 37376);
    float* rks = (float*)(sraw + 37632);
    float* lvs = (float*)(sraw + 37888);
    float* denP = (float*)(sraw + 38144);  // [2][64]

    int tid = threadIdx.x;
    int l = tid & 31, w = tid >> 5;
    int wq0 = (w >> 1) << 4;   // 0,16,32,48
    int wk0 = (w & 1) << 5;    // 0,32
    float tau = __expf(stau[0]);
    float gamma = sgam[0];

    uint32_t qBb = smem_u32(qB), kBb = smem_u32(kB);
    uint32_t vHb = smem_u32(vH), vLb = smem_u32(vL);
    uint32_t aAddrBase = qBb + (uint32_t)(wq0 + (l & 15)) * BROW + (uint32_t)((l >> 4) << 3) * 2;
    uint32_t bAddrBase = kBb + (uint32_t)(l & 7) * BROW + (uint32_t)(l & 8) * 2;
    uint32_t vRowOff = (uint32_t)(wk0 + (l & 15)) * BROW;

    // load q tile (bf16) + q aux
    {
        #pragma unroll
        for (int p = 0; p < 2; p++) {
            int idx = tid + 256 * p;
            int row = idx >> 3, c8 = (idx & 7) * 8;
            *(uint4*)((char*)qB + row * BROW + c8 * 2) =
                *(const uint4*)(&g_bf[0][(size_t)(q0 + row) * EM + h * HD + c8]);
        }
        if (tid < 64) {
            q2s[tid] = g_pt2[0][h * SQ + q0 + tid];
            rqs[tid] = g_rinv[0][h * SQ + q0 + tid];
        }
    }
    __syncthreads();

    int r0 = wq0 + (l >> 2), r1 = r0 + 8;
    float q2a0 = q2s[r0], rqa0 = rqs[r0];
    float q2a1 = q2s[r1], rqa1 = rqs[r1];
    int qg0 = q0 + r0, qg1 = q0 + r1;

    float Cn[8][4] = {};          // num accumulator, 16q x 64hd per warp (its key half)
    float den2_0 = 0.f, den2_1 = 0.f;

    for (int kt = 0; kt <= qt; kt++) {
        int k0 = kt * 64;
        {   // load k tile (bf16), v hi/lo tiles (bf16) + per-key aux
            #pragma unroll
            for (int p = 0; p < 2; p++) {
                int idx = tid + 256 * p;
                int row = idx >> 3, c8 = (idx & 7) * 8;
                size_t src = (size_t)(k0 + row) * EM + h * HD + c8;
                *(uint4*)((char*)kB + row * BROW + c8 * 2) = *(const uint4*)(&g_bf[1][src]);
                *(uint4*)((char*)vH + row * BROW + c8 * 2) = *(const uint4*)(&g_vhi[src]);
                *(uint4*)((char*)vL + row * BROW + c8 * 2) = *(const uint4*)(&g_vlo[src]);
            }
            if (tid < 64) {
                k2s[tid] = g_pt2[1][h * SQ + k0 + tid];
                rks[tid] = g_rinv[1][h * SQ + k0 + tid];
                lvs[tid] = 2.f * g_rinv[2][h * SQ + k0 + tid];
            }
        }
        __syncthreads();

        // phase 1: S = Q.K^T via bf16 mma (warp tile 16q x 32k over hd=64)
        float sc[4][4];
        #pragma unroll
        for (int nb = 0; nb < 4; nb++)
            #pragma unroll
            for (int i = 0; i < 4; i++) sc[nb][i] = 0.f;
        #pragma unroll
        for (int kc = 0; kc < 4; kc++) {
            uint32_t a0, a1, a2, a3;
            ldsm4(a0, a1, a2, a3, aAddrBase + kc * 32);
            #pragma unroll
            for (int nb = 0; nb < 4; nb++) {
                uint32_t b0, b1;
                ldsm2(b0, b1, bAddrBase + (uint32_t)(wk0 + nb * 8) * BROW + kc * 32);
                mma16816(sc[nb], a0, a1, a2, a3, b0, b1);
            }
        }

        // transform: distance -> exp weight -> wl split into bf16 A fragments
        uint32_t aHi[2][4], aLo[2][4];
        #pragma unroll
        for (int nb = 0; nb < 4; nb++) {
            int colb = wk0 + nb * 8 + ((l & 3) << 1);
            float2 k2p = *(float2*)&k2s[colb];
            float2 rkp = *(float2*)&rks[colb];
            float2 lvp = *(float2*)&lvs[colb];
            int kg = k0 + colb;
            float w00 = wfun(sc[nb][0], q2a0, rqa0, k2p.x, rkp.x, qg0, kg,     tau, gamma);
            float w01 = wfun(sc[nb][1], q2a0, rqa0, k2p.y, rkp.y, qg0, kg + 1, tau, gamma);
            float w10 = wfun(sc[nb][2], q2a1, rqa1, k2p.x, rkp.x, qg1, kg,     tau, gamma);
            float w11 = wfun(sc[nb][3], q2a1, rqa1, k2p.y, rkp.y, qg1, kg + 1, tau, gamma);
            float wl00 = w00 * lvp.x, wl01 = w01 * lvp.y;
            float wl10 = w10 * lvp.x, wl11 = w11 * lvp.y;
            den2_0 += (wl00 - w00) + (wl01 - w01);
            den2_1 += (wl10 - w10) + (wl11 - w11);
            __nv_bfloat16 h00 = __float2bfloat16(wl00), h01 = __float2bfloat16(wl01);
            __nv_bfloat16 h10 = __float2bfloat16(wl10), h11 = __float2bfloat16(wl11);
            __nv_bfloat16 e00 = __float2bfloat16(wl00 - __bfloat162float(h00));
            __nv_bfloat16 e01 = __float2bfloat16(wl01 - __bfloat162float(h01));
            __nv_bfloat16 e10 = __float2bfloat16(wl10 - __bfloat162float(h10));
            __nv_bfloat16 e11 = __float2bfloat16(wl11 - __bfloat162float(h11));
            int kc = nb >> 1, ri = (nb & 1) << 1;
            aHi[kc][ri + 0] = packbf(h00, h01);
            aHi[kc][ri + 1] = packbf(h10, h11);
            aLo[kc][ri + 0] = packbf(e00, e01);
            aLo[kc][ri + 1] = packbf(e10, e11);
        }

        // phase 2: num += W_l . V via mma (A = wl fragments, B = v hi/lo, 3-way split)
        #pragma unroll
        for (int kc = 0; kc < 2; kc++) {
            uint32_t rowAddrH = vHb + vRowOff + (uint32_t)(kc * 16) * BROW;
            uint32_t rowAddrL = vLb + vRowOff + (uint32_t)(kc * 16) * BROW;
            #pragma unroll
            for (int nt = 0; nt < 8; nt++) {
                uint32_t bh0, bh1, bl0, bl1;
                ldsm2t(bh0, bh1, rowAddrH + nt * 16);
                ldsm2t(bl0, bl1, rowAddrL + nt * 16);
                mma16816(Cn[nt], aHi[kc][0], aHi[kc][1], aHi[kc][2], aHi[kc][3], bh0, bh1);
                mma16816(Cn[nt], aHi[kc][0], aHi[kc][1], aHi[kc][2], aHi[kc][3], bl0, bl1);
                mma16816(Cn[nt], aLo[kc][0], aLo[kc][1], aLo[kc][2], aLo[kc][3], bh0, bh1);
            }
        }
        __syncthreads();
    }

    // fold den partials (quad lanes share rows), stage per key-half
    den2_0 += __shfl_xor_sync(0xffffffffu, den2_0, 1);
    den2_0 += __shfl_xor_sync(0xffffffffu, den2_0, 2);
    den2_1 += __shfl_xor_sync(0xffffffffu, den2_1, 1);
    den2_1 += __shfl_xor_sync(0xffffffffu, den2_1, 2);
    if ((l & 3) == 0) {
        denP[(w & 1) * 64 + r0] = den2_0;
        denP[(w & 1) * 64 + r1] = den2_1;
    }
    __syncthreads();

    // cross-warp num reduction: odd (wk0=32) warps stage, even warps add
    float* redS = (float*)sraw;  // 64 x RPAD, overlays qB/kB
    if (w & 1) {
        #pragma unroll
        for (int nt = 0; nt < 8; nt++) {
            int c = nt * 8 + ((l & 3) << 1);
            *(float2*)&redS[r0 * RPAD + c] = make_float2(Cn[nt][0], Cn[nt][1]);
            *(float2*)&redS[r1 * RPAD + c] = make_float2(Cn[nt][2], Cn[nt][3]);
        }
    }
    __syncthreads();
    if (!(w & 1)) {
        #pragma unroll
        for (int nt = 0; nt < 8; nt++) {
            int c = nt * 8 + ((l & 3) << 1);
            float2 p0 = *(float2*)&redS[r0 * RPAD + c];
            float2 p1 = *(float2*)&redS[r1 * RPAD + c];
            Cn[nt][0] += p0.x; Cn[nt][1] += p0.y;
            Cn[nt][2] += p1.x; Cn[nt][3] += p1.y;
        }
        // epilogue in fragment layout: rows r0, r1
        #pragma unroll
        for (int half = 0; half < 2; half++) {
            int r = half ? r1 : r0;
            float d = fmaxf(denP[r] + denP[64 + r], EPSF);
            float inv = 1.f / d;
            float gv[16];
            float gs = 0.f;
            #pragma unroll
            for (int nt = 0; nt < 8; nt++) {
                float g0 = Cn[nt][half * 2 + 0] * inv;
                float g1 = Cn[nt][half * 2 + 1] * inv;
                gv[nt * 2] = g0; gv[nt * 2 + 1] = g1;
                gs += g0 * g0 + g1 * g1;
            }
            gs += __shfl_xor_sync(0xffffffffu, gs, 1);
            gs += __shfl_xor_sync(0xffffffffu, gs, 2);
            float gn = fmaxf(sqrtf(gs), EPSF);
            float xc = fminf(gn, 1.f - 1e-7f);
            float tt = xc / (1.f + sqrtf(1.f - xc * xc));  // tanh(0.5*atanh(xc))
            float f = beta * tt / gn;
            float* orow = out + (size_t)(q0 + r) * EM + h * HD;
            #pragma unroll
            for (int nt = 0; nt < 8; nt++) {
                int c = nt * 8 + ((l & 3) << 1);
                *(float2*)&orow[c] = make_float2(f * gv[nt * 2], f * gv[nt * 2 + 1]);
            }
        }
    }
}

// ---------------- launch ----------------
extern "C" void kernel_launch(void* const* d_in, const int* in_sizes, int n_in,
                              void* d_out, int out_size) {
    const float* q  = (const float*)d_in[0];
    const float* k  = (const float*)d_in[1];
    const float* v  = (const float*)d_in[2];
    const float* Wq = (const float*)d_in[3];
    const float* Wk = (const float*)d_in[4];
    const float* Wv = (const float*)d_in[5];
    const float* bq = (const float*)d_in[6];
    const float* bk = (const float*)d_in[7];
    const float* bv = (const float*)d_in[8];
    const float* st = (const float*)d_in[9];
    const float* sg = (const float*)d_in[10];
    float* out = (float*)d_out;

    double lb = (lgamma(256.0) + lgamma(0.5) - lgamma(256.5))
              - (lgamma(32.0) + lgamma(0.5) - lgamma(32.5));
    float beta = (float)exp(lb);

    cudaFuncSetAttribute(attn_k, cudaFuncAttributeMaxDynamicSharedMemorySize, ATTN_SMEM_BYTES);

    colnorm_k<<<dim3(2, 3), 256>>>(Wq, Wk, Wv, bq, bk, bv);
    splitx_k<<<dim3(SQ, 3), 128>>>(q, k, v);
    splitw_k<<<dim3(EM, 3), 128>>>(Wq, Wk, Wv);
    proj_mma_k<<<dim3(EM / 64, SQ / 64, 3), 256>>>();
    normaux_k<<<dim3(SQ, 3), 128>>>();
    attn_k<<<(SQ / 64) * NH, 256, ATTN_SMEM_BYTES>>>(st, sg, beta, out);
    (void)in_sizes; (void)n_in; (void)out_size;
}

// round 15
// speedup vs baseline: 3.1981x; 1.0224x over previous
#include <cuda_runtime.h>
#include <cuda_bf16.h>
#include <stdint.h>
#include <math.h>

#define SQ 2048
#define EM 512
#define NH 8
#define HD 64
#define EPSF 1e-15f

// ---------------- scratch (static device globals; no allocation) ----------------
__device__ float g_proj[3][SQ * EM];            // projected+normalized q/k/v points, [S][E]
__device__ __nv_bfloat16 g_bf[2][SQ * EM];      // bf16 copies of q,k points for attn MMA
__device__ __nv_bfloat16 g_vhi[SQ * EM];        // v split: hi part
__device__ __nv_bfloat16 g_vlo[SQ * EM];        // v split: lo part
__device__ __nv_bfloat16 g_xhi[3][SQ * EM];     // input x split planes
__device__ __nv_bfloat16 g_xlo[3][SQ * EM];
__device__ __nv_bfloat16 g_whi[3][EM * EM];     // weight W split planes
__device__ __nv_bfloat16 g_wlo[3][EM * EM];
__device__ float g_x2[3][SQ];
__device__ float g_zn[3][EM];
__device__ float g_chv[3][EM];
__device__ float g_shv[3][EM];
__device__ float g_pt2[3][NH * SQ];
__device__ float g_rinv[3][NH * SQ];

// ---------------- helpers ----------------
__device__ __forceinline__ uint32_t smem_u32(const void* p) {
    return (uint32_t)__cvta_generic_to_shared(p);
}
__device__ __forceinline__ float sqrt_ap(float x) {
    float r; asm("sqrt.approx.f32 %0, %1;" : "=f"(r) : "f"(x)); return r;
}
__device__ __forceinline__ float rcp_ap(float x) {
    float r; asm("rcp.approx.f32 %0, %1;" : "=f"(r) : "f"(x)); return r;
}
__device__ __forceinline__ void ldsm4(uint32_t& a0, uint32_t& a1, uint32_t& a2, uint32_t& a3,
                                      uint32_t addr) {
    asm volatile("ldmatrix.sync.aligned.m8n8.x4.shared.b16 {%0,%1,%2,%3}, [%4];"
                 : "=r"(a0), "=r"(a1), "=r"(a2), "=r"(a3) : "r"(addr));
}
__device__ __forceinline__ void ldsm4t(uint32_t& a0, uint32_t& a1, uint32_t& a2, uint32_t& a3,
                                       uint32_t addr) {
    asm volatile("ldmatrix.sync.aligned.m8n8.x4.trans.shared.b16 {%0,%1,%2,%3}, [%4];"
                 : "=r"(a0), "=r"(a1), "=r"(a2), "=r"(a3) : "r"(addr));
}
__device__ __forceinline__ void mma16816(float* c, uint32_t a0, uint32_t a1, uint32_t a2,
                                         uint32_t a3, uint32_t b0, uint32_t b1) {
    asm volatile(
        "mma.sync.aligned.m16n8k16.row.col.f32.bf16.bf16.f32 "
        "{%0,%1,%2,%3}, {%4,%5,%6,%7}, {%8,%9}, {%0,%1,%2,%3};"
        : "+f"(c[0]), "+f"(c[1]), "+f"(c[2]), "+f"(c[3])
        : "r"(a0), "r"(a1), "r"(a2), "r"(a3), "r"(b0), "r"(b1));
}
__device__ __forceinline__ uint32_t packbf(__nv_bfloat16 a, __nv_bfloat16 b) {
    __nv_bfloat162 t; t.x = a; t.y = b;
    return *(uint32_t*)&t;
}

// ---------------- kernel 1: W column norms + bias cosh/sinh ----------------
__global__ void colnorm_k(const float* __restrict__ W0, const float* __restrict__ W1,
                          const float* __restrict__ W2, const float* __restrict__ b0,
                          const float* __restrict__ b1, const float* __restrict__ b2) {
    int t = blockIdx.y;
    int j = blockIdx.x * blockDim.x + threadIdx.x;
    if (j >= EM) return;
    const float* W = (t == 0) ? W0 : ((t == 1) ? W1 : W2);
    const float* b = (t == 0) ? b0 : ((t == 1) ? b1 : b2);
    float s = 0.f;
    for (int i = 0; i < EM; i++) { float v = W[i * EM + j]; s = fmaf(v, v, s); }
    float zn = fmaxf(sqrtf(s), EPSF);
    float r2 = 2.f * b[j];
    g_zn[t][j] = zn;
    g_chv[t][j] = coshf(r2);
    g_shv[t][j] = sinhf(r2);
}

// ---------------- kernel 2a: split inputs to bf16 hi/lo + row sumsq ----------------
__global__ void splitx_k(const float* __restrict__ x0, const float* __restrict__ x1,
                         const float* __restrict__ x2) {
    int t = blockIdx.y, s = blockIdx.x, tid = threadIdx.x;  // 128 threads
    const float* x = (t == 0) ? x0 : ((t == 1) ? x1 : x2);
    float4 v = ((const float4*)(x + (size_t)s * EM))[tid];
    float vv[4] = {v.x, v.y, v.z, v.w};
    float acc = v.x * v.x + v.y * v.y + v.z * v.z + v.w * v.w;
    #pragma unroll
    for (int m = 16; m; m >>= 1) acc += __shfl_xor_sync(0xffffffffu, acc, m);
    __shared__ float wsum[4];
    if ((tid & 31) == 0) wsum[tid >> 5] = acc;
    __nv_bfloat16* hdst = &g_xhi[t][(size_t)s * EM + tid * 4];
    __nv_bfloat16* ldst = &g_xlo[t][(size_t)s * EM + tid * 4];
    #pragma unroll
    for (int i = 0; i < 4; i++) {
        __nv_bfloat16 hi = __float2bfloat16(vv[i]);
        hdst[i] = hi;
        ldst[i] = __float2bfloat16(vv[i] - __bfloat162float(hi));
    }
    __syncthreads();
    if (tid == 0) g_x2[t][s] = wsum[0] + wsum[1] + wsum[2] + wsum[3];
}

// ---------------- kernel 2b: split weights to bf16 hi/lo ----------------
__global__ void splitw_k(const float* __restrict__ W0, const float* __restrict__ W1,
                         const float* __restrict__ W2) {
    int t = blockIdx.y, r = blockIdx.x, tid = threadIdx.x;  // 128 threads
    const float* W = (t == 0) ? W0 : ((t == 1) ? W1 : W2);
    float4 v = ((const float4*)(W + (size_t)r * EM))[tid];
    float vv[4] = {v.x, v.y, v.z, v.w};
    __nv_bfloat16* hdst = &g_whi[t][(size_t)r * EM + tid * 4];
    __nv_bfloat16* ldst = &g_wlo[t][(size_t)r * EM + tid * 4];
    #pragma unroll
    for (int i = 0; i < 4; i++) {
        __nv_bfloat16 hi = __float2bfloat16(vv[i]);
        hdst[i] = hi;
        ldst[i] = __float2bfloat16(vv[i] - __bfloat162float(hi));
    }
}

// ---------------- kernel 3: projection GEMM via bf16 MMA (3-term split) ----------------
#define BROW 144   // bf16 tile row stride in bytes (72 bf16)

__global__ __launch_bounds__(256) void proj_mma_k() {
    int t = blockIdx.z;
    int n0 = blockIdx.x * 64, m0 = blockIdx.y * 64;
    __shared__ __align__(16) char xHs[64 * BROW];
    __shared__ __align__(16) char xLs[64 * BROW];
    __shared__ __align__(16) char wHs[64 * BROW];
    __shared__ __align__(16) char wLs[64 * BROW];
    int tid = threadIdx.x;
    int l = tid & 31, w = tid >> 5;
    int wq0 = (w >> 1) << 4;   // m offset: 0,16,32,48
    int wk0 = (w & 1) << 5;    // n offset: 0,32

    uint32_t xHb = smem_u32(xHs), xLb = smem_u32(xLs);
    uint32_t wHb = smem_u32(wHs), wLb = smem_u32(wLs);
    uint32_t aOff = (uint32_t)(wq0 + (l & 15)) * BROW + (uint32_t)((l >> 4) << 3) * 2;
    // x4.trans B: lanes 0-15 rows k0..15 at col base; lanes 16-31 same rows, col +16B
    uint32_t bOff4 = (uint32_t)(l & 15) * BROW + (uint32_t)wk0 * 2 + (uint32_t)((l >> 4) << 4);

    float C[4][4] = {};  // 4 n-frags of 16x8

    for (int k0 = 0; k0 < EM; k0 += 64) {
        #pragma unroll
        for (int p = 0; p < 2; p++) {
            int idx = tid + 256 * p;
            int row = idx >> 3, c8 = (idx & 7) * 8;
            size_t xsrc = (size_t)(m0 + row) * EM + k0 + c8;
            size_t wsrc = (size_t)(k0 + row) * EM + n0 + c8;
            *(uint4*)(xHs + row * BROW + c8 * 2) = *(const uint4*)(&g_xhi[t][xsrc]);
            *(uint4*)(xLs + row * BROW + c8 * 2) = *(const uint4*)(&g_xlo[t][xsrc]);
            *(uint4*)(wHs + row * BROW + c8 * 2) = *(const uint4*)(&g_whi[t][wsrc]);
            *(uint4*)(wLs + row * BROW + c8 * 2) = *(const uint4*)(&g_wlo[t][wsrc]);
        }
        __syncthreads();
        #pragma unroll
        for (int kc = 0; kc < 4; kc++) {
            uint32_t ah0, ah1, ah2, ah3, al0, al1, al2, al3;
            ldsm4(ah0, ah1, ah2, ah3, xHb + aOff + kc * 32);
            ldsm4(al0, al1, al2, al3, xLb + aOff + kc * 32);
            #pragma unroll
            for (int nt2 = 0; nt2 < 2; nt2++) {
                uint32_t bAddr = bOff4 + (uint32_t)(kc * 16) * BROW + nt2 * 32;
                uint32_t bh0, bh1, bh2, bh3, bl0, bl1, bl2, bl3;
                ldsm4t(bh0, bh1, bh2, bh3, wHb + bAddr);
                ldsm4t(bl0, bl1, bl2, bl3, wLb + bAddr);
                mma16816(C[nt2 * 2 + 0], ah0, ah1, ah2, ah3, bh0, bh1);
                mma16816(C[nt2 * 2 + 1], ah0, ah1, ah2, ah3, bh2, bh3);
                mma16816(C[nt2 * 2 + 0], ah0, ah1, ah2, ah3, bl0, bl1);
                mma16816(C[nt2 * 2 + 1], ah0, ah1, ah2, ah3, bl2, bl3);
                mma16816(C[nt2 * 2 + 0], al0, al1, al2, al3, bh0, bh1);
                mma16816(C[nt2 * 2 + 1], al0, al1, al2, al3, bh2, bh3);
            }
        }
        __syncthreads();
    }

    // h_linear epilogue in fragment layout
    int r0 = wq0 + (l >> 2), r1 = r0 + 8;
    float lam0 = 2.f / (1.f - g_x2[t][m0 + r0]);
    float lam1 = 2.f / (1.f - g_x2[t][m0 + r1]);
    #pragma unroll
    for (int nt = 0; nt < 4; nt++) {
        int c = n0 + wk0 + nt * 8 + ((l & 3) << 1);
        float2 zn2 = *(float2*)&g_zn[t][c];
        float2 ch2 = *(float2*)&g_chv[t][c];
        float2 sh2 = *(float2*)&g_shv[t][c];
        float rzn0 = 1.f / zn2.x, rzn1 = 1.f / zn2.y;
        float vals[4] = {C[nt][0], C[nt][1], C[nt][2], C[nt][3]};
        float res[4];
        #pragma unroll
        for (int q = 0; q < 4; q++) {
            float lam = (q < 2) ? lam0 : lam1;
            float rzn = (q & 1) ? rzn1 : rzn0;
            float ch = (q & 1) ? ch2.y : ch2.x;
            float sh = (q & 1) ? sh2.y : sh2.x;
            float zn = (q & 1) ? zn2.y : zn2.x;
            float arg = (vals[q] * lam * rzn) * ch - (lam - 1.f) * sh;
            float as = __logf(arg + sqrt_ap(fmaf(arg, arg, 1.f)));   // asinh
            float dd = 2.f * zn * as;
            float e = __expf(dd);
            res[q] = 0.5f * (e - 1.f / e);                            // sinh
        }
        *(float2*)&g_proj[t][(size_t)(m0 + r0) * EM + c] = make_float2(res[0], res[1]);
        *(float2*)&g_proj[t][(size_t)(m0 + r1) * EM + c] = make_float2(res[2], res[3]);
    }
}

// ---------------- kernel 4: ball normalization + per-head aux + bf16 planes ----------------
__global__ void normaux_k() {
    int t = blockIdx.y, s = blockIdx.x, tid = threadIdx.x;  // 128 threads
    float* row = &g_proj[t][(size_t)s * EM];
    float4 v = ((float4*)row)[tid];
    float l4 = v.x * v.x + v.y * v.y + v.z * v.z + v.w * v.w;
    float tot = l4;
    #pragma unroll
    for (int m = 16; m; m >>= 1) tot += __shfl_xor_sync(0xffffffffu, tot, m);
    __shared__ float wsum[4];
    if ((tid & 31) == 0) wsum[tid >> 5] = tot;
    __syncthreads();
    float total = wsum[0] + wsum[1] + wsum[2] + wsum[3];
    float scale = 1.f / (1.f + sqrtf(1.f + total));
    v.x *= scale; v.y *= scale; v.z *= scale; v.w *= scale;
    ((float4*)row)[tid] = v;
    float vv[4] = {v.x, v.y, v.z, v.w};
    if (t < 2) {
        __nv_bfloat16* bdst = &g_bf[t][(size_t)s * EM + tid * 4];
        #pragma unroll
        for (int i = 0; i < 4; i++) bdst[i] = __float2bfloat16(vv[i]);
    } else {
        __nv_bfloat16* hdst = &g_vhi[(size_t)s * EM + tid * 4];
        __nv_bfloat16* ldst = &g_vlo[(size_t)s * EM + tid * 4];
        #pragma unroll
        for (int i = 0; i < 4; i++) {
            __nv_bfloat16 hi = __float2bfloat16(vv[i]);
            hdst[i] = hi;
            ldst[i] = __float2bfloat16(vv[i] - __bfloat162float(hi));
        }
    }
    float hs = l4;
    #pragma unroll
    for (int m = 8; m; m >>= 1) hs += __shfl_xor_sync(0xffffffffu, hs, m);
    if ((tid & 15) == 0) {
        int h = tid >> 4;
        float pt2 = scale * scale * hs;
        g_pt2[t][h * SQ + s] = pt2;
        g_rinv[t][h * SQ + s] = 1.f / (1.f - pt2);
    }
}

// ---------------- kernel 5: causal hyperbolic attention (full-MMA) ----------------
#define ATTN_SMEM_BYTES 38656
#define RPAD 68

// w = exp(-tau*acosh(arg) - gamma); z = arg + sqrt((arg-1)(arg+1))
// fast path (tau==1): w = exp(-gamma) / z
__device__ __forceinline__ float wfun(float qk, float q2, float rq, float k2, float rk,
                                      int qg, int kg, float tau, float egam, bool fastp) {
    if (kg > qg) return 0.f;
    float d2 = fmaxf(q2 + k2 - 2.f * qk, 0.f);
    float arg = fmaf(2.f * d2, rq * rk, 1.f);
    arg = fmaxf(arg, 1.f + 1e-7f);
    float z = arg + sqrt_ap((arg - 1.f) * (arg + 1.f));
    if (fastp) return egam * rcp_ap(z);
    return egam * __expf(-tau * __logf(z));
}

__global__ __launch_bounds__(256) void attn_k(const float* __restrict__ stau,
                                              const float* __restrict__ sgam,
                                              float beta, float* __restrict__ out) {
    int bid = blockIdx.x;
    int h = bid & (NH - 1);
    int qt = (SQ / 64 - 1) - (bid >> 3);
    int q0 = qt * 64;
    extern __shared__ char sraw[];
    __nv_bfloat16* qB = (__nv_bfloat16*)sraw;
    __nv_bfloat16* kB = (__nv_bfloat16*)(sraw + 9216);
    __nv_bfloat16* vH = (__nv_bfloat16*)(sraw + 18432);
    __nv_bfloat16* vL = (__nv_bfloat16*)(sraw + 27648);
    float* q2s = (float*)(sraw + 36864);
    float* rqs = (float*)(sraw + 37120);
    float* k2s = (float*)(sraw + 37376);
    float* rks = (float*)(sraw + 37632);
    float* lvs = (float*)(sraw + 37888);
    float* denP = (float*)(sraw + 38144);  // [2][64]

    int tid = threadIdx.x;
    int l = tid & 31, w = tid >> 5;
    int wq0 = (w >> 1) << 4;   // 0,16,32,48
    int wk0 = (w & 1) << 5;    // 0,32
    float tau = __expf(stau[0]);
    float egam = __expf(-sgam[0]);
    bool fastp = (tau == 1.0f);

    uint32_t qBb = smem_u32(qB), kBb = smem_u32(kB);
    uint32_t vHb = smem_u32(vH), vLb = smem_u32(vL);
    uint32_t aAddrBase = qBb + (uint32_t)(wq0 + (l & 15)) * BROW + (uint32_t)((l >> 4) << 3) * 2;
    // x4 non-trans B for phase 1: lanes 0-7 rows n0-7/k0-7, 8-15 n0-7/k8-15, 16-23 n8-15/k0-7, 24-31 n8-15/k8-15
    uint32_t b4Off = (uint32_t)((l & 7) + ((l & 16) >> 1)) * BROW + (uint32_t)(l & 8) * 2;
    // x4 trans B for phase 2: lanes 0-15 rows at col base; 16-31 same rows, col +16B
    uint32_t vOff4 = (uint32_t)(wk0 + (l & 15)) * BROW + (uint32_t)((l >> 4) << 4);

    // load q tile (bf16) + q aux
    {
        #pragma unroll
        for (int p = 0; p < 2; p++) {
            int idx = tid + 256 * p;
            int row = idx >> 3, c8 = (idx & 7) * 8;
            *(uint4*)((char*)qB + row * BROW + c8 * 2) =
                *(const uint4*)(&g_bf[0][(size_t)(q0 + row) * EM + h * HD + c8]);
        }
        if (tid < 64) {
            q2s[tid] = g_pt2[0][h * SQ + q0 + tid];
            rqs[tid] = g_rinv[0][h * SQ + q0 + tid];
        }
    }
    __syncthreads();

    int r0 = wq0 + (l >> 2), r1 = r0 + 8;
    float q2a0 = q2s[r0], rqa0 = rqs[r0];
    float q2a1 = q2s[r1], rqa1 = rqs[r1];
    int qg0 = q0 + r0, qg1 = q0 + r1;

    float Cn[8][4] = {};          // num accumulator, 16q x 64hd per warp (its key half)
    float den2_0 = 0.f, den2_1 = 0.f;

    for (int kt = 0; kt <= qt; kt++) {
        int k0 = kt * 64;
        {   // load k tile (bf16), v hi/lo tiles (bf16) + per-key aux
            #pragma unroll
            for (int p = 0; p < 2; p++) {
                int idx = tid + 256 * p;
                int row = idx >> 3, c8 = (idx & 7) * 8;
                size_t src = (size_t)(k0 + row) * EM + h * HD + c8;
                *(uint4*)((char*)kB + row * BROW + c8 * 2) = *(const uint4*)(&g_bf[1][src]);
                *(uint4*)((char*)vH + row * BROW + c8 * 2) = *(const uint4*)(&g_vhi[src]);
                *(uint4*)((char*)vL + row * BROW + c8 * 2) = *(const uint4*)(&g_vlo[src]);
            }
            if (tid < 64) {
                k2s[tid] = g_pt2[1][h * SQ + k0 + tid];
                rks[tid] = g_rinv[1][h * SQ + k0 + tid];
                lvs[tid] = 2.f * g_rinv[2][h * SQ + k0 + tid];
            }
        }
        __syncthreads();

        // phase 1: S = Q.K^T via bf16 mma (warp tile 16q x 32k over hd=64)
        float sc[4][4];
        #pragma unroll
        for (int nb = 0; nb < 4; nb++)
            #pragma unroll
            for (int i = 0; i < 4; i++) sc[nb][i] = 0.f;
        #pragma unroll
        for (int kc = 0; kc < 4; kc++) {
            uint32_t a0, a1, a2, a3;
            ldsm4(a0, a1, a2, a3, aAddrBase + kc * 32);
            #pragma unroll
            for (int nb2 = 0; nb2 < 2; nb2++) {
                uint32_t b0, b1, b2, b3;
                ldsm4(b0, b1, b2, b3,
                      kBb + b4Off + (uint32_t)(wk0 + nb2 * 16) * BROW + kc * 32);
                mma16816(sc[nb2 * 2 + 0], a0, a1, a2, a3, b0, b1);
                mma16816(sc[nb2 * 2 + 1], a0, a1, a2, a3, b2, b3);
            }
        }

        // transform: distance -> exp weight -> wl split into bf16 A fragments
        uint32_t aHi[2][4], aLo[2][4];
        #pragma unroll
        for (int nb = 0; nb < 4; nb++) {
            int colb = wk0 + nb * 8 + ((l & 3) << 1);
            float2 k2p = *(float2*)&k2s[colb];
            float2 rkp = *(float2*)&rks[colb];
            float2 lvp = *(float2*)&lvs[colb];
            int kg = k0 + colb;
            float w00 = wfun(sc[nb][0], q2a0, rqa0, k2p.x, rkp.x, qg0, kg,     tau, egam, fastp);
            float w01 = wfun(sc[nb][1], q2a0, rqa0, k2p.y, rkp.y, qg0, kg + 1, tau, egam, fastp);
            float w10 = wfun(sc[nb][2], q2a1, rqa1, k2p.x, rkp.x, qg1, kg,     tau, egam, fastp);
            float w11 = wfun(sc[nb][3], q2a1, rqa1, k2p.y, rkp.y, qg1, kg + 1, tau, egam, fastp);
            float wl00 = w00 * lvp.x, wl01 = w01 * lvp.y;
            float wl10 = w10 * lvp.x, wl11 = w11 * lvp.y;
            den2_0 += (wl00 - w00) + (wl01 - w01);
            den2_1 += (wl10 - w10) + (wl11 - w11);
            __nv_bfloat16 h00 = __float2bfloat16(wl00), h01 = __float2bfloat16(wl01);
            __nv_bfloat16 h10 = __float2bfloat16(wl10), h11 = __float2bfloat16(wl11);
            __nv_bfloat16 e00 = __float2bfloat16(wl00 - __bfloat162float(h00));
            __nv_bfloat16 e01 = __float2bfloat16(wl01 - __bfloat162float(h01));
            __nv_bfloat16 e10 = __float2bfloat16(wl10 - __bfloat162float(h10));
            __nv_bfloat16 e11 = __float2bfloat16(wl11 - __bfloat162float(h11));
            int kc = nb >> 1, ri = (nb & 1) << 1;
            aHi[kc][ri + 0] = packbf(h00, h01);
            aHi[kc][ri + 1] = packbf(h10, h11);
            aLo[kc][ri + 0] = packbf(e00, e01);
            aLo[kc][ri + 1] = packbf(e10, e11);
        }

        // phase 2: num += W_l . V via mma (A = wl fragments, B = v hi/lo, 3-way split)
        #pragma unroll
        for (int kc = 0; kc < 2; kc++) {
            uint32_t baseH = vHb + vOff4 + (uint32_t)(kc * 16) * BROW;
            uint32_t baseL = vLb + vOff4 + (uint32_t)(kc * 16) * BROW;
            #pragma unroll
            for (int nt2 = 0; nt2 < 4; nt2++) {
                uint32_t bh0, bh1, bh2, bh3, bl0, bl1, bl2, bl3;
                ldsm4t(bh0, bh1, bh2, bh3, baseH + nt2 * 32);
                ldsm4t(bl0, bl1, bl2, bl3, baseL + nt2 * 32);
                mma16816(Cn[nt2 * 2 + 0], aHi[kc][0], aHi[kc][1], aHi[kc][2], aHi[kc][3], bh0, bh1);
                mma16816(Cn[nt2 * 2 + 1], aHi[kc][0], aHi[kc][1], aHi[kc][2], aHi[kc][3], bh2, bh3);
                mma16816(Cn[nt2 * 2 + 0], aHi[kc][0], aHi[kc][1], aHi[kc][2], aHi[kc][3], bl0, bl1);
                mma16816(Cn[nt2 * 2 + 1], aHi[kc][0], aHi[kc][1], aHi[kc][2], aHi[kc][3], bl2, bl3);
                mma16816(Cn[nt2 * 2 + 0], aLo[kc][0], aLo[kc][1], aLo[kc][2], aLo[kc][3], bh0, bh1);
                mma16816(Cn[nt2 * 2 + 1], aLo[kc][0], aLo[kc][1], aLo[kc][2], aLo[kc][3], bh2, bh3);
            }
        }
        __syncthreads();
    }

    // fold den partials (quad lanes share rows), stage per key-half
    den2_0 += __shfl_xor_sync(0xffffffffu, den2_0, 1);
    den2_0 += __shfl_xor_sync(0xffffffffu, den2_0, 2);
    den2_1 += __shfl_xor_sync(0xffffffffu, den2_1, 1);
    den2_1 += __shfl_xor_sync(0xffffffffu, den2_1, 2);
    if ((l & 3) == 0) {
        denP[(w & 1) * 64 + r0] = den2_0;
        denP[(w & 1) * 64 + r1] = den2_1;
    }
    __syncthreads();

    // cross-warp num reduction: odd (wk0=32) warps stage, even warps add
    float* redS = (float*)sraw;  // 64 x RPAD, overlays qB/kB
    if (w & 1) {
        #pragma unroll
        for (int nt = 0; nt < 8; nt++) {
            int c = nt * 8 + ((l & 3) << 1);
            *(float2*)&redS[r0 * RPAD + c] = make_float2(Cn[nt][0], Cn[nt][1]);
            *(float2*)&redS[r1 * RPAD + c] = make_float2(Cn[nt][2], Cn[nt][3]);
        }
    }
    __syncthreads();
    if (!(w & 1)) {
        #pragma unroll
        for (int nt = 0; nt < 8; nt++) {
            int c = nt * 8 + ((l & 3) << 1);
            float2 p0 = *(float2*)&redS[r0 * RPAD + c];
            float2 p1 = *(float2*)&redS[r1 * RPAD + c];
            Cn[nt][0] += p0.x; Cn[nt][1] += p0.y;
            Cn[nt][2] += p1.x; Cn[nt][3] += p1.y;
        }
        // epilogue in fragment layout: rows r0, r1
        #pragma unroll
        for (int half = 0; half < 2; half++) {
            int r = half ? r1 : r0;
            float d = fmaxf(denP[r] + denP[64 + r], EPSF);
            float inv = 1.f / d;
            float gv[16];
            float gs = 0.f;
            #pragma unroll
            for (int nt = 0; nt < 8; nt++) {
                float g0 = Cn[nt][half * 2 + 0] * inv;
                float g1 = Cn[nt][half * 2 + 1] * inv;
                gv[nt * 2] = g0; gv[nt * 2 + 1] = g1;
                gs += g0 * g0 + g1 * g1;
            }
            gs += __shfl_xor_sync(0xffffffffu, gs, 1);
            gs += __shfl_xor_sync(0xffffffffu, gs, 2);
            float gn = fmaxf(sqrtf(gs), EPSF);
            float xc = fminf(gn, 1.f - 1e-7f);
            float tt = xc / (1.f + sqrtf(1.f - xc * xc));  // tanh(0.5*atanh(xc))
            float f = beta * tt / gn;
            float* orow = out + (size_t)(q0 + r) * EM + h * HD;
            #pragma unroll
            for (int nt = 0; nt < 8; nt++) {
                int c = nt * 8 + ((l & 3) << 1);
                *(float2*)&orow[c] = make_float2(f * gv[nt * 2], f * gv[nt * 2 + 1]);
            }
        }
    }
}

// ---------------- launch ----------------
extern "C" void kernel_launch(void* const* d_in, const int* in_sizes, int n_in,
                              void* d_out, int out_size) {
    const float* q  = (const float*)d_in[0];
    const float* k  = (const float*)d_in[1];
    const float* v  = (const float*)d_in[2];
    const float* Wq = (const float*)d_in[3];
    const float* Wk = (const float*)d_in[4];
    const float* Wv = (const float*)d_in[5];
    const float* bq = (const float*)d_in[6];
    const float* bk = (const float*)d_in[7];
    const float* bv = (const float*)d_in[8];
    const float* st = (const float*)d_in[9];
    const float* sg = (const float*)d_in[10];
    float* out = (float*)d_out;

    double lb = (lgamma(256.0) + lgamma(0.5) - lgamma(256.5))
              - (lgamma(32.0) + lgamma(0.5) - lgamma(32.5));
    float beta = (float)exp(lb);

    cudaFuncSetAttribute(attn_k, cudaFuncAttributeMaxDynamicSharedMemorySize, ATTN_SMEM_BYTES);

    colnorm_k<<<dim3(2, 3), 256>>>(Wq, Wk, Wv, bq, bk, bv);
    splitx_k<<<dim3(SQ, 3), 128>>>(q, k, v);
    splitw_k<<<dim3(EM, 3), 128>>>(Wq, Wk, Wv);
    proj_mma_k<<<dim3(EM / 64, SQ / 64, 3), 256>>>();
    normaux_k<<<dim3(SQ, 3), 128>>>();
    attn_k<<<(SQ / 64) * NH, 256, ATTN_SMEM_BYTES>>>(st, sg, beta, out);
    (void)in_sizes; (void)n_in; (void)out_size;
}

// round 16
// speedup vs baseline: 3.4552x; 1.0804x over previous
#include <cuda_runtime.h>
#include <cuda_bf16.h>
#include <stdint.h>
#include <math.h>

#define SQ 2048
#define EM 512
#define NH 8
#define HD 64
#define EPSF 1e-15f

// ---------------- scratch (static device globals; no allocation) ----------------
__device__ float g_proj[3][SQ * EM];            // projected+normalized q/k/v points, [S][E]
__device__ __nv_bfloat16 g_bf[2][SQ * EM];      // bf16 copies of q,k points for attn MMA
__device__ __nv_bfloat16 g_vhi[SQ * EM];        // v split: hi part
__device__ __nv_bfloat16 g_vlo[SQ * EM];        // v split: lo part
__device__ __nv_bfloat16 g_xhi[3][SQ * EM];     // input x split planes
__device__ __nv_bfloat16 g_xlo[3][SQ * EM];
__device__ __nv_bfloat16 g_whi[3][EM * EM];     // weight W split planes
__device__ __nv_bfloat16 g_wlo[3][EM * EM];
__device__ float g_x2[3][SQ];
__device__ float g_zn[3][EM];
__device__ float g_chv[3][EM];
__device__ float g_shv[3][EM];
__device__ float g_pt2[3][NH * SQ];
__device__ float g_rinv[3][NH * SQ];

// ---------------- helpers ----------------
__device__ __forceinline__ uint32_t smem_u32(const void* p) {
    return (uint32_t)__cvta_generic_to_shared(p);
}
__device__ __forceinline__ float sqrt_ap(float x) {
    float r; asm("sqrt.approx.f32 %0, %1;" : "=f"(r) : "f"(x)); return r;
}
__device__ __forceinline__ float rcp_ap(float x) {
    float r; asm("rcp.approx.f32 %0, %1;" : "=f"(r) : "f"(x)); return r;
}
__device__ __forceinline__ void cp16(uint32_t dst, const void* src) {
    asm volatile("cp.async.cg.shared.global [%0], [%1], 16;" :: "r"(dst), "l"(src));
}
__device__ __forceinline__ void cp_commit() {
    asm volatile("cp.async.commit_group;");
}
__device__ __forceinline__ void cp_wait1() {
    asm volatile("cp.async.wait_group 1;");
}
__device__ __forceinline__ void ldsm4(uint32_t& a0, uint32_t& a1, uint32_t& a2, uint32_t& a3,
                                      uint32_t addr) {
    asm volatile("ldmatrix.sync.aligned.m8n8.x4.shared.b16 {%0,%1,%2,%3}, [%4];"
                 : "=r"(a0), "=r"(a1), "=r"(a2), "=r"(a3) : "r"(addr));
}
__device__ __forceinline__ void ldsm4t(uint32_t& a0, uint32_t& a1, uint32_t& a2, uint32_t& a3,
                                       uint32_t addr) {
    asm volatile("ldmatrix.sync.aligned.m8n8.x4.trans.shared.b16 {%0,%1,%2,%3}, [%4];"
                 : "=r"(a0), "=r"(a1), "=r"(a2), "=r"(a3) : "r"(addr));
}
__device__ __forceinline__ void mma16816(float* c, uint32_t a0, uint32_t a1, uint32_t a2,
                                         uint32_t a3, uint32_t b0, uint32_t b1) {
    asm volatile(
        "mma.sync.aligned.m16n8k16.row.col.f32.bf16.bf16.f32 "
        "{%0,%1,%2,%3}, {%4,%5,%6,%7}, {%8,%9}, {%0,%1,%2,%3};"
        : "+f"(c[0]), "+f"(c[1]), "+f"(c[2]), "+f"(c[3])
        : "r"(a0), "r"(a1), "r"(a2), "r"(a3), "r"(b0), "r"(b1));
}
__device__ __forceinline__ uint32_t packbf(__nv_bfloat16 a, __nv_bfloat16 b) {
    __nv_bfloat162 t; t.x = a; t.y = b;
    return *(uint32_t*)&t;
}

// ---------------- kernel 1: W column norms + bias cosh/sinh ----------------
__global__ void colnorm_k(const float* __restrict__ W0, const float* __restrict__ W1,
                          const float* __restrict__ W2, const float* __restrict__ b0,
                          const float* __restrict__ b1, const float* __restrict__ b2) {
    int t = blockIdx.y;
    int j = blockIdx.x * blockDim.x + threadIdx.x;
    if (j >= EM) return;
    const float* W = (t == 0) ? W0 : ((t == 1) ? W1 : W2);
    const float* b = (t == 0) ? b0 : ((t == 1) ? b1 : b2);
    float s = 0.f;
    for (int i = 0; i < EM; i++) { float v = W[i * EM + j]; s = fmaf(v, v, s); }
    float zn = fmaxf(sqrtf(s), EPSF);
    float r2 = 2.f * b[j];
    g_zn[t][j] = zn;
    g_chv[t][j] = coshf(r2);
    g_shv[t][j] = sinhf(r2);
}

// ---------------- kernel 2a: split inputs to bf16 hi/lo + row sumsq ----------------
__global__ void splitx_k(const float* __restrict__ x0, const float* __restrict__ x1,
                         const float* __restrict__ x2) {
    int t = blockIdx.y, s = blockIdx.x, tid = threadIdx.x;  // 128 threads
    const float* x = (t == 0) ? x0 : ((t == 1) ? x1 : x2);
    float4 v = ((const float4*)(x + (size_t)s * EM))[tid];
    float vv[4] = {v.x, v.y, v.z, v.w};
    float acc = v.x * v.x + v.y * v.y + v.z * v.z + v.w * v.w;
    #pragma unroll
    for (int m = 16; m; m >>= 1) acc += __shfl_xor_sync(0xffffffffu, acc, m);
    __shared__ float wsum[4];
    if ((tid & 31) == 0) wsum[tid >> 5] = acc;
    __nv_bfloat16* hdst = &g_xhi[t][(size_t)s * EM + tid * 4];
    __nv_bfloat16* ldst = &g_xlo[t][(size_t)s * EM + tid * 4];
    #pragma unroll
    for (int i = 0; i < 4; i++) {
        __nv_bfloat16 hi = __float2bfloat16(vv[i]);
        hdst[i] = hi;
        ldst[i] = __float2bfloat16(vv[i] - __bfloat162float(hi));
    }
    __syncthreads();
    if (tid == 0) g_x2[t][s] = wsum[0] + wsum[1] + wsum[2] + wsum[3];
}

// ---------------- kernel 2b: split weights to bf16 hi/lo ----------------
__global__ void splitw_k(const float* __restrict__ W0, const float* __restrict__ W1,
                         const float* __restrict__ W2) {
    int t = blockIdx.y, r = blockIdx.x, tid = threadIdx.x;  // 128 threads
    const float* W = (t == 0) ? W0 : ((t == 1) ? W1 : W2);
    float4 v = ((const float4*)(W + (size_t)r * EM))[tid];
    float vv[4] = {v.x, v.y, v.z, v.w};
    __nv_bfloat16* hdst = &g_whi[t][(size_t)r * EM + tid * 4];
    __nv_bfloat16* ldst = &g_wlo[t][(size_t)r * EM + tid * 4];
    #pragma unroll
    for (int i = 0; i < 4; i++) {
        __nv_bfloat16 hi = __float2bfloat16(vv[i]);
        hdst[i] = hi;
        ldst[i] = __float2bfloat16(vv[i] - __bfloat162float(hi));
    }
}

// ---------------- kernel 3: projection GEMM via bf16 MMA (3-term split, pipelined) ----------------
#define BROW 144           // bf16 tile row stride in bytes (72 bf16)
#define PST 36864          // proj stage stride: 4 tiles x 9216B
#define PROJ_SMEM_BYTES (2 * PST)

__global__ __launch_bounds__(256) void proj_mma_k() {
    int t = blockIdx.z;
    int n0 = blockIdx.x * 64, m0 = blockIdx.y * 64;
    extern __shared__ char psm[];
    uint32_t psb = smem_u32(psm);
    int tid = threadIdx.x;
    int l = tid & 31, w = tid >> 5;
    int wq0 = (w >> 1) << 4;   // m offset: 0,16,32,48
    int wk0 = (w & 1) << 5;    // n offset: 0,32

    uint32_t aOff = (uint32_t)(wq0 + (l & 15)) * BROW + (uint32_t)((l >> 4) << 3) * 2;
    uint32_t bOff4 = (uint32_t)(l & 15) * BROW + (uint32_t)wk0 * 2 + (uint32_t)((l >> 4) << 4);

    int row = tid >> 3, c8 = (tid & 7) * 8;  // loader lane mapping (p adds 32 rows)

    // issue loads for chunk 0 into stage 0
    {
        #pragma unroll
        for (int p = 0; p < 2; p++) {
            int r2 = row + 32 * p;
            size_t xsrc = (size_t)(m0 + r2) * EM + c8;
            size_t wsrc = (size_t)r2 * EM + n0 + c8;
            uint32_t d = psb + (uint32_t)(r2 * BROW + c8 * 2);
            cp16(d + 0,     &g_xhi[t][xsrc]);
            cp16(d + 9216,  &g_xlo[t][xsrc]);
            cp16(d + 18432, &g_whi[t][wsrc]);
            cp16(d + 27648, &g_wlo[t][wsrc]);
        }
        cp_commit();
    }

    float C[4][4] = {};  // 4 n-frags of 16x8

    for (int c = 0; c < 8; c++) {
        int s = c & 1;
        if (c < 7) {  // prefetch chunk c+1 into the other stage
            int k0n = (c + 1) * 64;
            uint32_t sb = psb + (uint32_t)((s ^ 1) * PST);
            #pragma unroll
            for (int p = 0; p < 2; p++) {
                int r2 = row + 32 * p;
                size_t xsrc = (size_t)(m0 + r2) * EM + k0n + c8;
                size_t wsrc = (size_t)(k0n + r2) * EM + n0 + c8;
                uint32_t d = sb + (uint32_t)(r2 * BROW + c8 * 2);
                cp16(d + 0,     &g_xhi[t][xsrc]);
                cp16(d + 9216,  &g_xlo[t][xsrc]);
                cp16(d + 18432, &g_whi[t][wsrc]);
                cp16(d + 27648, &g_wlo[t][wsrc]);
            }
        }
        cp_commit();
        cp_wait1();
        __syncthreads();

        uint32_t xHb = psb + (uint32_t)(s * PST);
        uint32_t xLb = xHb + 9216;
        uint32_t wHb = xHb + 18432;
        uint32_t wLb = xHb + 27648;
        #pragma unroll
        for (int kc = 0; kc < 4; kc++) {
            uint32_t ah0, ah1, ah2, ah3, al0, al1, al2, al3;
            ldsm4(ah0, ah1, ah2, ah3, xHb + aOff + kc * 32);
            ldsm4(al0, al1, al2, al3, xLb + aOff + kc * 32);
            #pragma unroll
            for (int nt2 = 0; nt2 < 2; nt2++) {
                uint32_t bAddr = bOff4 + (uint32_t)(kc * 16) * BROW + nt2 * 32;
                uint32_t bh0, bh1, bh2, bh3, bl0, bl1, bl2, bl3;
                ldsm4t(bh0, bh1, bh2, bh3, wHb + bAddr);
                ldsm4t(bl0, bl1, bl2, bl3, wLb + bAddr);
                mma16816(C[nt2 * 2 + 0], ah0, ah1, ah2, ah3, bh0, bh1);
                mma16816(C[nt2 * 2 + 1], ah0, ah1, ah2, ah3, bh2, bh3);
                mma16816(C[nt2 * 2 + 0], ah0, ah1, ah2, ah3, bl0, bl1);
                mma16816(C[nt2 * 2 + 1], ah0, ah1, ah2, ah3, bl2, bl3);
                mma16816(C[nt2 * 2 + 0], al0, al1, al2, al3, bh0, bh1);
                mma16816(C[nt2 * 2 + 1], al0, al1, al2, al3, bh2, bh3);
            }
        }
        __syncthreads();
    }

    // h_linear epilogue in fragment layout
    int r0 = wq0 + (l >> 2), r1 = r0 + 8;
    float lam0 = 2.f / (1.f - g_x2[t][m0 + r0]);
    float lam1 = 2.f / (1.f - g_x2[t][m0 + r1]);
    #pragma unroll
    for (int nt = 0; nt < 4; nt++) {
        int c = n0 + wk0 + nt * 8 + ((l & 3) << 1);
        float2 zn2 = *(float2*)&g_zn[t][c];
        float2 ch2 = *(float2*)&g_chv[t][c];
        float2 sh2 = *(float2*)&g_shv[t][c];
        float rzn0 = 1.f / zn2.x, rzn1 = 1.f / zn2.y;
        float vals[4] = {C[nt][0], C[nt][1], C[nt][2], C[nt][3]};
        float res[4];
        #pragma unroll
        for (int q = 0; q < 4; q++) {
            float lam = (q < 2) ? lam0 : lam1;
            float rzn = (q & 1) ? rzn1 : rzn0;
            float ch = (q & 1) ? ch2.y : ch2.x;
            float sh = (q & 1) ? sh2.y : sh2.x;
            float zn = (q & 1) ? zn2.y : zn2.x;
            float arg = (vals[q] * lam * rzn) * ch - (lam - 1.f) * sh;
            float as = __logf(arg + sqrt_ap(fmaf(arg, arg, 1.f)));   // asinh
            float dd = 2.f * zn * as;
            float e = __expf(dd);
            res[q] = 0.5f * (e - 1.f / e);                            // sinh
        }
        *(float2*)&g_proj[t][(size_t)(m0 + r0) * EM + c] = make_float2(res[0], res[1]);
        *(float2*)&g_proj[t][(size_t)(m0 + r1) * EM + c] = make_float2(res[2], res[3]);
    }
}

// ---------------- kernel 4: ball normalization + per-head aux + bf16 planes ----------------
__global__ void normaux_k() {
    int t = blockIdx.y, s = blockIdx.x, tid = threadIdx.x;  // 128 threads
    float* row = &g_proj[t][(size_t)s * EM];
    float4 v = ((float4*)row)[tid];
    float l4 = v.x * v.x + v.y * v.y + v.z * v.z + v.w * v.w;
    float tot = l4;
    #pragma unroll
    for (int m = 16; m; m >>= 1) tot += __shfl_xor_sync(0xffffffffu, tot, m);
    __shared__ float wsum[4];
    if ((tid & 31) == 0) wsum[tid >> 5] = tot;
    __syncthreads();
    float total = wsum[0] + wsum[1] + wsum[2] + wsum[3];
    float scale = 1.f / (1.f + sqrtf(1.f + total));
    v.x *= scale; v.y *= scale; v.z *= scale; v.w *= scale;
    ((float4*)row)[tid] = v;
    float vv[4] = {v.x, v.y, v.z, v.w};
    if (t < 2) {
        __nv_bfloat16* bdst = &g_bf[t][(size_t)s * EM + tid * 4];
        #pragma unroll
        for (int i = 0; i < 4; i++) bdst[i] = __float2bfloat16(vv[i]);
    } else {
        __nv_bfloat16* hdst = &g_vhi[(size_t)s * EM + tid * 4];
        __nv_bfloat16* ldst = &g_vlo[(size_t)s * EM + tid * 4];
        #pragma unroll
        for (int i = 0; i < 4; i++) {
            __nv_bfloat16 hi = __float2bfloat16(vv[i]);
            hdst[i] = hi;
            ldst[i] = __float2bfloat16(vv[i] - __bfloat162float(hi));
        }
    }
    float hs = l4;
    #pragma unroll
    for (int m = 8; m; m >>= 1) hs += __shfl_xor_sync(0xffffffffu, hs, m);
    if ((tid & 15) == 0) {
        int h = tid >> 4;
        float pt2 = scale * scale * hs;
        g_pt2[t][h * SQ + s] = pt2;
        g_rinv[t][h * SQ + s] = 1.f / (1.f - pt2);
    }
}

// ---------------- kernel 5: causal hyperbolic attention (full-MMA, pipelined) ----------------
// smem layout (bytes):
//  qB @0 (9216)
//  stage s (s=0,1): kB @9216+s*27648, vH @+9216, vL @+18432   (ends 64512)
//  q2s @64512, rqs @64768
//  aux stage s @65024+s*768: k2s +0, rks +256, rvs +512       (ends 66560)
//  denP [2][64] @66560                                         (ends 67072)
//  redS (f32 64x68) overlays @0 after the k-loop
#define ATTN_SMEM_BYTES 67072
#define AST 27648
#define RPAD 68

// w = exp(-tau*acosh(arg) - gamma); z = arg + sqrt((arg-1)(arg+1))
// fast path (tau==1): w = exp(-gamma) / z
__device__ __forceinline__ float wfun(float qk, float q2, float rq, float k2, float rk,
                                      int qg, int kg, float tau, float egam, bool fastp) {
    if (kg > qg) return 0.f;
    float d2 = fmaxf(q2 + k2 - 2.f * qk, 0.f);
    float arg = fmaf(2.f * d2, rq * rk, 1.f);
    arg = fmaxf(arg, 1.f + 1e-7f);
    float z = arg + sqrt_ap((arg - 1.f) * (arg + 1.f));
    if (fastp) return egam * rcp_ap(z);
    return egam * __expf(-tau * __logf(z));
}

__global__ __launch_bounds__(256) void attn_k(const float* __restrict__ stau,
                                              const float* __restrict__ sgam,
                                              float beta, float* __restrict__ out) {
    int bid = blockIdx.x;
    int h = bid & (NH - 1);
    int qt = (SQ / 64 - 1) - (bid >> 3);
    int q0 = qt * 64;
    extern __shared__ char sraw[];
    uint32_t sb = smem_u32(sraw);
    float* q2s = (float*)(sraw + 64512);
    float* rqs = (float*)(sraw + 64768);
    float* denP = (float*)(sraw + 66560);  // [2][64]

    int tid = threadIdx.x;
    int l = tid & 31, w = tid >> 5;
    int wq0 = (w >> 1) << 4;   // 0,16,32,48
    int wk0 = (w & 1) << 5;    // 0,32
    float tau = __expf(stau[0]);
    float egam = __expf(-sgam[0]);
    bool fastp = (tau == 1.0f);

    uint32_t aAddrBase = sb + (uint32_t)(wq0 + (l & 15)) * BROW + (uint32_t)((l >> 4) << 3) * 2;
    uint32_t b4Off = (uint32_t)((l & 7) + ((l & 16) >> 1)) * BROW + (uint32_t)(l & 8) * 2;
    uint32_t vOff4 = (uint32_t)(wk0 + (l & 15)) * BROW + (uint32_t)((l >> 4) << 4);

    int lrow = tid >> 3, lc8 = (tid & 7) * 8;  // loader mapping (p adds 32 rows)

    // issue k/v loads for kt=0 into stage 0 + aux
    {
        uint32_t st0 = sb + 9216;
        #pragma unroll
        for (int p = 0; p < 2; p++) {
            int r2 = lrow + 32 * p;
            size_t src = (size_t)r2 * EM + h * HD + lc8;
            uint32_t d = st0 + (uint32_t)(r2 * BROW + lc8 * 2);
            cp16(d + 0,     &g_bf[1][src]);
            cp16(d + 9216,  &g_vhi[src]);
            cp16(d + 18432, &g_vlo[src]);
        }
        if (tid < 48) {
            int grp = tid >> 4, sl = tid & 15;
            uint32_t d = sb + 65024 + (uint32_t)(grp * 256 + sl * 16);
            const float* src = (grp == 0) ? &g_pt2[1][h * SQ + sl * 4]
                             : (grp == 1) ? &g_rinv[1][h * SQ + sl * 4]
                                          : &g_rinv[2][h * SQ + sl * 4];
            cp16(d, src);
        }
        cp_commit();
    }

    // load q tile (bf16) + q aux (regular loads)
    {
        #pragma unroll
        for (int p = 0; p < 2; p++) {
            int r2 = lrow + 32 * p;
            *(uint4*)(sraw + r2 * BROW + lc8 * 2) =
                *(const uint4*)(&g_bf[0][(size_t)(q0 + r2) * EM + h * HD + lc8]);
        }
        if (tid < 64) {
            q2s[tid] = g_pt2[0][h * SQ + q0 + tid];
            rqs[tid] = g_rinv[0][h * SQ + q0 + tid];
        }
    }

    int r0 = wq0 + (l >> 2), r1 = r0 + 8;
    int qg0 = q0 + r0, qg1 = q0 + r1;

    float Cn[8][4] = {};          // num accumulator, 16q x 64hd per warp (its key half)
    float den2_0 = 0.f, den2_1 = 0.f;
    float q2a0 = 0.f, rqa0 = 0.f, q2a1 = 0.f, rqa1 = 0.f;

    for (int kt = 0; kt <= qt; kt++) {
        int s = kt & 1;
        if (kt < qt) {  // prefetch kt+1 into the other stage
            int k0n = (kt + 1) * 64;
            uint32_t stn = sb + 9216 + (uint32_t)((s ^ 1) * AST);
            #pragma unroll
            for (int p = 0; p < 2; p++) {
                int r2 = lrow + 32 * p;
                size_t src = (size_t)(k0n + r2) * EM + h * HD + lc8;
                uint32_t d = stn + (uint32_t)(r2 * BROW + lc8 * 2);
                cp16(d + 0,     &g_bf[1][src]);
                cp16(d + 9216,  &g_vhi[src]);
                cp16(d + 18432, &g_vlo[src]);
            }
            if (tid < 48) {
                int grp = tid >> 4, sl = tid & 15;
                uint32_t d = sb + 65024 + (uint32_t)((s ^ 1) * 768 + grp * 256 + sl * 16);
                const float* src = (grp == 0) ? &g_pt2[1][h * SQ + k0n + sl * 4]
                                 : (grp == 1) ? &g_rinv[1][h * SQ + k0n + sl * 4]
                                              : &g_rinv[2][h * SQ + k0n + sl * 4];
                cp16(d, src);
            }
        }
        cp_commit();
        cp_wait1();
        __syncthreads();

        if (kt == 0) {  // q aux now visible
            q2a0 = q2s[r0]; rqa0 = rqs[r0];
            q2a1 = q2s[r1]; rqa1 = rqs[r1];
        }
        int k0 = kt * 64;
        uint32_t kBb = sb + 9216 + (uint32_t)(s * AST);
        uint32_t vHb = kBb + 9216, vLb = kBb + 18432;
        float* k2s = (float*)(sraw + 65024 + s * 768);
        float* rks = k2s + 64;
        float* rvs = k2s + 128;

        // phase 1: S = Q.K^T via bf16 mma (warp tile 16q x 32k over hd=64)
        float sc[4][4];
        #pragma unroll
        for (int nb = 0; nb < 4; nb++)
            #pragma unroll
            for (int i = 0; i < 4; i++) sc[nb][i] = 0.f;
        #pragma unroll
        for (int kc = 0; kc < 4; kc++) {
            uint32_t a0, a1, a2, a3;
            ldsm4(a0, a1, a2, a3, aAddrBase + kc * 32);
            #pragma unroll
            for (int nb2 = 0; nb2 < 2; nb2++) {
                uint32_t b0, b1, b2, b3;
                ldsm4(b0, b1, b2, b3,
                      kBb + b4Off + (uint32_t)(wk0 + nb2 * 16) * BROW + kc * 32);
                mma16816(sc[nb2 * 2 + 0], a0, a1, a2, a3, b0, b1);
                mma16816(sc[nb2 * 2 + 1], a0, a1, a2, a3, b2, b3);
            }
        }

        // transform: distance -> exp weight -> wl split into bf16 A fragments
        uint32_t aHi[2][4], aLo[2][4];
        #pragma unroll
        for (int nb = 0; nb < 4; nb++) {
            int colb = wk0 + nb * 8 + ((l & 3) << 1);
            float2 k2p = *(float2*)&k2s[colb];
            float2 rkp = *(float2*)&rks[colb];
            float2 rvp = *(float2*)&rvs[colb];
            int kg = k0 + colb;
            float w00 = wfun(sc[nb][0], q2a0, rqa0, k2p.x, rkp.x, qg0, kg,     tau, egam, fastp);
            float w01 = wfun(sc[nb][1], q2a0, rqa0, k2p.y, rkp.y, qg0, kg + 1, tau, egam, fastp);
            float w10 = wfun(sc[nb][2], q2a1, rqa1, k2p.x, rkp.x, qg1, kg,     tau, egam, fastp);
            float w11 = wfun(sc[nb][3], q2a1, rqa1, k2p.y, rkp.y, qg1, kg + 1, tau, egam, fastp);
            float lv0 = 2.f * rvp.x, lv1 = 2.f * rvp.y;
            float wl00 = w00 * lv0, wl01 = w01 * lv1;
            float wl10 = w10 * lv0, wl11 = w11 * lv1;
            den2_0 += (wl00 - w00) + (wl01 - w01);
            den2_1 += (wl10 - w10) + (wl11 - w11);
            __nv_bfloat16 h00 = __float2bfloat16(wl00), h01 = __float2bfloat16(wl01);
            __nv_bfloat16 h10 = __float2bfloat16(wl10), h11 = __float2bfloat16(wl11);
            __nv_bfloat16 e00 = __float2bfloat16(wl00 - __bfloat162float(h00));
            __nv_bfloat16 e01 = __float2bfloat16(wl01 - __bfloat162float(h01));
            __nv_bfloat16 e10 = __float2bfloat16(wl10 - __bfloat162float(h10));
            __nv_bfloat16 e11 = __float2bfloat16(wl11 - __bfloat162float(h11));
            int kc = nb >> 1, ri = (nb & 1) << 1;
            aHi[kc][ri + 0] = packbf(h00, h01);
            aHi[kc][ri + 1] = packbf(h10, h11);
            aLo[kc][ri + 0] = packbf(e00, e01);
            aLo[kc][ri + 1] = packbf(e10, e11);
        }

        // phase 2: num += W_l . V via mma (A = wl fragments, B = v hi/lo, 3-way split)
        #pragma unroll
        for (int kc = 0; kc < 2; kc++) {
            uint32_t baseH = vHb + vOff4 + (uint32_t)(kc * 16) * BROW;
            uint32_t baseL = vLb + vOff4 + (uint32_t)(kc * 16) * BROW;
            #pragma unroll
            for (int nt2 = 0; nt2 < 4; nt2++) {
                uint32_t bh0, bh1, bh2, bh3, bl0, bl1, bl2, bl3;
                ldsm4t(bh0, bh1, bh2, bh3, baseH + nt2 * 32);
                ldsm4t(bl0, bl1, bl2, bl3, baseL + nt2 * 32);
                mma16816(Cn[nt2 * 2 + 0], aHi[kc][0], aHi[kc][1], aHi[kc][2], aHi[kc][3], bh0, bh1);
                mma16816(Cn[nt2 * 2 + 1], aHi[kc][0], aHi[kc][1], aHi[kc][2], aHi[kc][3], bh2, bh3);
                mma16816(Cn[nt2 * 2 + 0], aHi[kc][0], aHi[kc][1], aHi[kc][2], aHi[kc][3], bl0, bl1);
                mma16816(Cn[nt2 * 2 + 1], aHi[kc][0], aHi[kc][1], aHi[kc][2], aHi[kc][3], bl2, bl3);
                mma16816(Cn[nt2 * 2 + 0], aLo[kc][0], aLo[kc][1], aLo[kc][2], aLo[kc][3], bh0, bh1);
                mma16816(Cn[nt2 * 2 + 1], aLo[kc][0], aLo[kc][1], aLo[kc][2], aLo[kc][3], bh2, bh3);
            }
        }
        __syncthreads();
    }

    // fold den partials (quad lanes share rows), stage per key-half
    den2_0 += __shfl_xor_sync(0xffffffffu, den2_0, 1);
    den2_0 += __shfl_xor_sync(0xffffffffu, den2_0, 2);
    den2_1 += __shfl_xor_sync(0xffffffffu, den2_1, 1);
    den2_1 += __shfl_xor_sync(0xffffffffu, den2_1, 2);
    if ((l & 3) == 0) {
        denP[(w & 1) * 64 + r0] = den2_0;
        denP[(w & 1) * 64 + r1] = den2_1;
    }
    __syncthreads();

    // cross-warp num reduction: odd (wk0=32) warps stage, even warps add
    float* redS = (float*)sraw;  // 64 x RPAD, overlays qB/stage0
    if (w & 1) {
        #pragma unroll
        for (int nt = 0; nt < 8; nt++) {
            int c = nt * 8 + ((l & 3) << 1);
            *(float2*)&redS[r0 * RPAD + c] = make_float2(Cn[nt][0], Cn[nt][1]);
            *(float2*)&redS[r1 * RPAD + c] = make_float2(Cn[nt][2], Cn[nt][3]);
        }
    }
    __syncthreads();
    if (!(w & 1)) {
        #pragma unroll
        for (int nt = 0; nt < 8; nt++) {
            int c = nt * 8 + ((l & 3) << 1);
            float2 p0 = *(float2*)&redS[r0 * RPAD + c];
            float2 p1 = *(float2*)&redS[r1 * RPAD + c];
            Cn[nt][0] += p0.x; Cn[nt][1] += p0.y;
            Cn[nt][2] += p1.x; Cn[nt][3] += p1.y;
        }
        // epilogue in fragment layout: rows r0, r1
        #pragma unroll
        for (int half = 0; half < 2; half++) {
            int r = half ? r1 : r0;
            float d = fmaxf(denP[r] + denP[64 + r], EPSF);
            float inv = 1.f / d;
            float gv[16];
            float gs = 0.f;
            #pragma unroll
            for (int nt = 0; nt < 8; nt++) {
                float g0 = Cn[nt][half * 2 + 0] * inv;
                float g1 = Cn[nt][half * 2 + 1] * inv;
                gv[nt * 2] = g0; gv[nt * 2 + 1] = g1;
                gs += g0 * g0 + g1 * g1;
            }
            gs += __shfl_xor_sync(0xffffffffu, gs, 1);
            gs += __shfl_xor_sync(0xffffffffu, gs, 2);
            float gn = fmaxf(sqrtf(gs), EPSF);
            float xc = fminf(gn, 1.f - 1e-7f);
            float tt = xc / (1.f + sqrtf(1.f - xc * xc));  // tanh(0.5*atanh(xc))
            float f = beta * tt / gn;
            float* orow = out + (size_t)(q0 + r) * EM + h * HD;
            #pragma unroll
            for (int nt = 0; nt < 8; nt++) {
                int c = nt * 8 + ((l & 3) << 1);
                *(float2*)&orow[c] = make_float2(f * gv[nt * 2], f * gv[nt * 2 + 1]);
            }
        }
    }
}

// ---------------- launch ----------------
extern "C" void kernel_launch(void* const* d_in, const int* in_sizes, int n_in,
                              void* d_out, int out_size) {
    const float* q  = (const float*)d_in[0];
    const float* k  = (const float*)d_in[1];
    const float* v  = (const float*)d_in[2];
    const float* Wq = (const float*)d_in[3];
    const float* Wk = (const float*)d_in[4];
    const float* Wv = (const float*)d_in[5];
    const float* bq = (const float*)d_in[6];
    const float* bk = (const float*)d_in[7];
    const float* bv = (const float*)d_in[8];
    const float* st = (const float*)d_in[9];
    const float* sg = (const float*)d_in[10];
    float* out = (float*)d_out;

    double lb = (lgamma(256.0) + lgamma(0.5) - lgamma(256.5))
              - (lgamma(32.0) + lgamma(0.5) - lgamma(32.5));
    float beta = (float)exp(lb);

    cudaFuncSetAttribute(attn_k, cudaFuncAttributeMaxDynamicSharedMemorySize, ATTN_SMEM_BYTES);
    cudaFuncSetAttribute(proj_mma_k, cudaFuncAttributeMaxDynamicSharedMemorySize,
                         PROJ_SMEM_BYTES);

    colnorm_k<<<dim3(2, 3), 256>>>(Wq, Wk, Wv, bq, bk, bv);
    splitx_k<<<dim3(SQ, 3), 128>>>(q, k, v);
    splitw_k<<<dim3(EM, 3), 128>>>(Wq, Wk, Wv);
    proj_mma_k<<<dim3(EM / 64, SQ / 64, 3), 256, PROJ_SMEM_BYTES>>>();
    normaux_k<<<dim3(SQ, 3), 128>>>();
    attn_k<<<(SQ / 64) * NH, 256, ATTN_SMEM_BYTES>>>(st, sg, beta, out);
    (void)in_sizes; (void)n_in; (void)out_size;
}